// round 2
// baseline (speedup 1.0000x reference)
#include <cuda_runtime.h>
#include <math.h>

#define S_SYS 32
#define N_ATOM 512
#define F_DIM 256
#define R_EXCL 5.0f

// Scratch (allocation-free rule: __device__ globals)
__device__ float g_charges[S_SYS * N_ATOM * F_DIM];   // 16 MB
__device__ float g_v[(size_t)S_SYS * N_ATOM * N_ATOM]; // 32 MB

// ---------------------------------------------------------------------------
// GEMM1: charges[m][n] = sum_k features[m][k] * W[n][k] + b[n]
// M=16384, N=256, K=256. BM=BN=64, BK=16, 256 threads, 4x4 microtile.
// ---------------------------------------------------------------------------
__global__ __launch_bounds__(256) void gemm1_kernel(
    const float* __restrict__ A,   // features [M, K] row-major
    const float* __restrict__ W,   // [F, F] row-major (we use W^T)
    const float* __restrict__ bias,
    float* __restrict__ C)
{
    const int BM = 64, BN = 64, BK = 16;
    __shared__ float As[BK][BM + 4];
    __shared__ float Bs[BK][BN + 4];

    int t  = threadIdx.x;
    int tx = t & 15;        // 0..15 -> n micro
    int ty = t >> 4;        // 0..15 -> m micro
    int m0 = blockIdx.y * BM;
    int n0 = blockIdx.x * BN;

    float acc[4][4] = {};

    for (int k0 = 0; k0 < F_DIM; k0 += BK) {
        // A tile: 64 rows x 16 k = 256 float4 loads, one per thread
        {
            int m = t >> 2, kq = t & 3;
            float4 v4 = *(const float4*)(A + (size_t)(m0 + m) * F_DIM + k0 + kq * 4);
            As[kq * 4 + 0][m] = v4.x;
            As[kq * 4 + 1][m] = v4.y;
            As[kq * 4 + 2][m] = v4.z;
            As[kq * 4 + 3][m] = v4.w;
        }
        // B tile: Bs[k][n] = W[(n0+n)*F + k0+k]
        {
            int n = t >> 2, kq = t & 3;
            float4 v4 = *(const float4*)(W + (size_t)(n0 + n) * F_DIM + k0 + kq * 4);
            Bs[kq * 4 + 0][n] = v4.x;
            Bs[kq * 4 + 1][n] = v4.y;
            Bs[kq * 4 + 2][n] = v4.z;
            Bs[kq * 4 + 3][n] = v4.w;
        }
        __syncthreads();

        #pragma unroll
        for (int k = 0; k < BK; ++k) {
            float a[4], bfr[4];
            #pragma unroll
            for (int i = 0; i < 4; ++i) a[i] = As[k][ty * 4 + i];
            #pragma unroll
            for (int j = 0; j < 4; ++j) bfr[j] = Bs[k][tx * 4 + j];
            #pragma unroll
            for (int i = 0; i < 4; ++i)
                #pragma unroll
                for (int j = 0; j < 4; ++j)
                    acc[i][j] = fmaf(a[i], bfr[j], acc[i][j]);
        }
        __syncthreads();
    }

    #pragma unroll
    for (int i = 0; i < 4; ++i) {
        int m = m0 + ty * 4 + i;
        #pragma unroll
        for (int j = 0; j < 4; ++j) {
            int n = n0 + tx * 4 + j;
            C[(size_t)m * F_DIM + n] = acc[i][j] + bias[n];
        }
    }
}

// ---------------------------------------------------------------------------
// Pair potential matrix: v[s][i][j]
// v = (1/d) * (1 - fcut), fcut = 0.5*(1+cos(pi*d/R)) for d < R, 0 on diagonal
// One block per (i, s). Positions of system s staged into shared.
// ---------------------------------------------------------------------------
__global__ __launch_bounds__(128) void pair_kernel(
    const float* __restrict__ pos,    // [S, N, 3]
    float* __restrict__ V)            // [S, N, N]
{
    __shared__ float sx[N_ATOM], sy[N_ATOM], sz[N_ATOM];
    int s = blockIdx.y;
    int i = blockIdx.x;
    const float* ps = pos + (size_t)s * N_ATOM * 3;

    for (int j = threadIdx.x; j < N_ATOM; j += blockDim.x) {
        sx[j] = ps[j * 3 + 0];
        sy[j] = ps[j * 3 + 1];
        sz[j] = ps[j * 3 + 2];
    }
    __syncthreads();

    float xi = sx[i], yi = sy[i], zi = sz[i];
    float* vrow = V + ((size_t)s * N_ATOM + i) * N_ATOM;
    const float c = (float)M_PI / R_EXCL;

    for (int j = threadIdx.x; j < N_ATOM; j += blockDim.x) {
        float dx = xi - sx[j];
        float dy = yi - sy[j];
        float dz = zi - sz[j];
        float d2 = dx * dx + dy * dy + dz * dz;
        float d  = sqrtf(d2);
        float val;
        if (j == i) {
            val = 0.0f;
        } else {
            float fcut = (d < R_EXCL) ? 0.5f * (1.0f + cosf(c * d)) : 0.0f;
            val = (1.0f - fcut) / d;
        }
        vrow[j] = val;
    }
}

// ---------------------------------------------------------------------------
// GEMM2 (batched over s): out[s][m][n] = (0.5 * sum_j v[s][m][j]*q[s][j][n]) * q[s][m][n]
// M=512, N=256, K=512 per batch. Same tiling as GEMM1.
// ---------------------------------------------------------------------------
__global__ __launch_bounds__(256) void gemm2_kernel(
    const float* __restrict__ Vmat,   // [S, N, N]
    const float* __restrict__ Q,      // [S, N, F] (= g_charges)
    float* __restrict__ out)          // [S*N, F]
{
    const int BM = 64, BN = 64, BK = 16;
    __shared__ float As[BK][BM + 4];
    __shared__ float Bs[BK][BN + 4];

    int s = blockIdx.z;
    const float* A = Vmat + (size_t)s * N_ATOM * N_ATOM;
    const float* B = Q + (size_t)s * N_ATOM * F_DIM;

    int t  = threadIdx.x;
    int tx = t & 15;
    int ty = t >> 4;
    int m0 = blockIdx.y * BM;
    int n0 = blockIdx.x * BN;

    float acc[4][4] = {};

    for (int k0 = 0; k0 < N_ATOM; k0 += BK) {
        // A tile (row-major, k contiguous): 64 m x 16 k
        {
            int m = t >> 2, kq = t & 3;
            float4 v4 = *(const float4*)(A + (size_t)(m0 + m) * N_ATOM + k0 + kq * 4);
            As[kq * 4 + 0][m] = v4.x;
            As[kq * 4 + 1][m] = v4.y;
            As[kq * 4 + 2][m] = v4.z;
            As[kq * 4 + 3][m] = v4.w;
        }
        // B tile: Bs[k][n] = Q[(k0+k)*F + n0+n], n contiguous
        {
            int k = t >> 4, nq = t & 15;
            float4 v4 = *(const float4*)(B + (size_t)(k0 + k) * F_DIM + n0 + nq * 4);
            Bs[k][nq * 4 + 0] = v4.x;
            Bs[k][nq * 4 + 1] = v4.y;
            Bs[k][nq * 4 + 2] = v4.z;
            Bs[k][nq * 4 + 3] = v4.w;
        }
        __syncthreads();

        #pragma unroll
        for (int k = 0; k < BK; ++k) {
            float a[4], bfr[4];
            #pragma unroll
            for (int i = 0; i < 4; ++i) a[i] = As[k][ty * 4 + i];
            #pragma unroll
            for (int j = 0; j < 4; ++j) bfr[j] = Bs[k][tx * 4 + j];
            #pragma unroll
            for (int i = 0; i < 4; ++i)
                #pragma unroll
                for (int j = 0; j < 4; ++j)
                    acc[i][j] = fmaf(a[i], bfr[j], acc[i][j]);
        }
        __syncthreads();
    }

    // Epilogue: multiply by q[m][n] and 0.5
    #pragma unroll
    for (int i = 0; i < 4; ++i) {
        int m = m0 + ty * 4 + i;
        #pragma unroll
        for (int j = 0; j < 4; ++j) {
            int n = n0 + tx * 4 + j;
            float qmn = B[(size_t)m * F_DIM + n];
            out[((size_t)s * N_ATOM + m) * F_DIM + n] = 0.5f * acc[i][j] * qmn;
        }
    }
}

// ---------------------------------------------------------------------------
extern "C" void kernel_launch(void* const* d_in, const int* in_sizes, int n_in,
                              void* d_out, int out_size)
{
    const float* positions = (const float*)d_in[0]; // [32, 512, 3]
    const float* features  = (const float*)d_in[1]; // [16384, 256]
    const float* W         = (const float*)d_in[2]; // [256, 256]
    const float* b         = (const float*)d_in[3]; // [256]
    float* out             = (float*)d_out;         // [16384, 256]

    float* charges;
    float* vmat;
    cudaGetSymbolAddress((void**)&charges, g_charges);
    cudaGetSymbolAddress((void**)&vmat, g_v);

    // GEMM1: charges = features @ W^T + b
    {
        dim3 grid(F_DIM / 64, (S_SYS * N_ATOM) / 64); // (4, 256)
        gemm1_kernel<<<grid, 256>>>(features, W, b, charges);
    }
    // Pair potential matrices (independent of GEMM1; same stream serializes)
    {
        dim3 grid(N_ATOM, S_SYS); // (512, 32)
        pair_kernel<<<grid, 128>>>(positions, vmat);
    }
    // Batched GEMM2 + fused epilogue
    {
        dim3 grid(F_DIM / 64, N_ATOM / 64, S_SYS); // (4, 8, 32)
        gemm2_kernel<<<grid, 256>>>(vmat, charges, out);
    }
}

// round 5
// speedup vs baseline: 2.1947x; 2.1947x over previous
#include <cuda_runtime.h>
#include <cuda_bf16.h>
#include <cstdint>
#include <math.h>

#define S_SYS 32
#define N_ATOM 512
#define F_DIM 256
#define R_EXCL 5.0f

// Scratch (__device__ globals; allocation-free rule). bf16 stored as uint16.
__device__ __align__(16) uint16_t g_vhi[(size_t)S_SYS * N_ATOM * N_ATOM]; // 16 MB
__device__ __align__(16) uint16_t g_vlo[(size_t)S_SYS * N_ATOM * N_ATOM]; // 16 MB
__device__ __align__(16) uint16_t g_qhi[(size_t)S_SYS * F_DIM * N_ATOM];  // 8 MB  (q^T hi)
__device__ __align__(16) uint16_t g_qlo[(size_t)S_SYS * F_DIM * N_ATOM];  // 8 MB  (q^T lo)

// ---------------------------------------------------------------------------
// helpers
// ---------------------------------------------------------------------------
__device__ __forceinline__ uint32_t smem_u32(const void* p) {
    uint32_t a;
    asm("{ .reg .u64 t; cvta.to.shared.u64 t, %1; cvt.u32.u64 %0, t; }" : "=r"(a) : "l"(p));
    return a;
}
// pack two floats to bf16x2, first arg in LOW half
__device__ __forceinline__ uint32_t pack_bf16(float lo_elem, float hi_elem) {
    uint32_t r;
    asm("cvt.rn.bf16x2.f32 %0, %1, %2;" : "=r"(r) : "f"(hi_elem), "f"(lo_elem));
    return r;
}
__device__ __forceinline__ float bf_lo(uint32_t p) { return __uint_as_float(p << 16); }
__device__ __forceinline__ float bf_hi(uint32_t p) { return __uint_as_float(p & 0xFFFF0000u); }

__device__ __forceinline__ void mma16816(float* c, uint32_t a0, uint32_t a1, uint32_t a2,
                                         uint32_t a3, uint32_t b0, uint32_t b1) {
    asm volatile(
        "mma.sync.aligned.m16n8k16.row.col.f32.bf16.bf16.f32 "
        "{%0,%1,%2,%3}, {%4,%5,%6,%7}, {%8,%9}, {%0,%1,%2,%3};"
        : "+f"(c[0]), "+f"(c[1]), "+f"(c[2]), "+f"(c[3])
        : "r"(a0), "r"(a1), "r"(a2), "r"(a3), "r"(b0), "r"(b1));
}
__device__ __forceinline__ void ldsm4(uint32_t* r, uint32_t addr) {
    asm volatile("ldmatrix.sync.aligned.m8n8.x4.shared.b16 {%0,%1,%2,%3}, [%4];"
                 : "=r"(r[0]), "=r"(r[1]), "=r"(r[2]), "=r"(r[3]) : "r"(addr));
}
#define CP_ASYNC16(dst, src) \
    asm volatile("cp.async.cg.shared.global [%0], [%1], 16;" :: "r"(dst), "l"(src))
#define CP_COMMIT() asm volatile("cp.async.commit_group;" ::: "memory")
#define CP_WAIT(n)  asm volatile("cp.async.wait_group %0;" :: "n"(n) : "memory")

// smem tile layout: 128 rows x 32 bf16 (64B) at 80B stride -> 10240 B per tile
#define T_AH 0
#define T_AL 10240
#define T_BH 20480
#define T_BL 30720
#define STAGE 40960

// ---------------------------------------------------------------------------
// GEMM2: per system s: D[m,f] = sum_j v[m,j] q[j,f];  out = 0.5*D*q[m,f]
// A = v (hi/lo bf16, row m, k=j contiguous), B = q^T (hi/lo, row f, k=j contig)
// BM=128, BN=128, BK=32, 256 threads, warp tile 64x32. cp.async double buffer.
// ---------------------------------------------------------------------------
__global__ __launch_bounds__(256, 2) void gemm2_mma(
    const uint16_t* __restrict__ vhi, const uint16_t* __restrict__ vlo,
    const uint16_t* __restrict__ qhi, const uint16_t* __restrict__ qlo,
    float* __restrict__ out)
{
    extern __shared__ char sm[];
    const int t = threadIdx.x, lane = t & 31, w = t >> 5;
    const int wm = (w & 1) * 64, wn = (w >> 1) * 32;
    const int s = blockIdx.z, m0 = blockIdx.y * 128, f0 = blockIdx.x * 128;
    const uint32_t sb = smem_u32(sm);

    const char* Ah = (const char*)(vhi + ((size_t)s * N_ATOM + m0) * N_ATOM);
    const char* Al = (const char*)(vlo + ((size_t)s * N_ATOM + m0) * N_ATOM);
    const char* Bh = (const char*)(qhi + ((size_t)s * F_DIM + f0) * N_ATOM);
    const char* Bl = (const char*)(qlo + ((size_t)s * F_DIM + f0) * N_ATOM);
    // global row stride = 512 bf16 = 1024 bytes

    float c[4][4][4] = {};

    const int row_ld = (t + 0) >> 2;          // cp.async: thread -> (row, seg)
    const int seg_ld = (t & 3) * 16;

    // prefetch chunk 0
    {
        const int koff = 0;
        #pragma unroll
        for (int j = 0; j < 2; ++j) {
            int row = row_ld + j * 64;
            uint32_t d = sb + (uint32_t)(row * 80 + seg_ld);
            size_t g = (size_t)row * 1024 + koff + seg_ld;
            CP_ASYNC16(d + T_AH, Ah + g);
            CP_ASYNC16(d + T_AL, Al + g);
            CP_ASYNC16(d + T_BH, Bh + g);
            CP_ASYNC16(d + T_BL, Bl + g);
        }
        CP_COMMIT();
    }

    const int mrow = (lane & 7) + ((lane >> 3) & 1) * 8;
    const int kb   = (lane >> 4) * 16;

    for (int ch = 0; ch < 16; ++ch) {
        if (ch + 1 < 16) {
            const int koff = (ch + 1) * 64;
            const uint32_t st = sb + ((ch + 1) & 1) * STAGE;
            #pragma unroll
            for (int j = 0; j < 2; ++j) {
                int row = row_ld + j * 64;
                uint32_t d = st + (uint32_t)(row * 80 + seg_ld);
                size_t g = (size_t)row * 1024 + koff + seg_ld;
                CP_ASYNC16(d + T_AH, Ah + g);
                CP_ASYNC16(d + T_AL, Al + g);
                CP_ASYNC16(d + T_BH, Bh + g);
                CP_ASYNC16(d + T_BL, Bl + g);
            }
            CP_COMMIT();
            CP_WAIT(1);
        } else {
            CP_WAIT(0);
        }
        __syncthreads();

        const uint32_t st = sb + (ch & 1) * STAGE;
        #pragma unroll
        for (int ks = 0; ks < 2; ++ks) {
            #pragma unroll
            for (int split = 0; split < 3; ++split) {
                const uint32_t aoff = (split == 2) ? (uint32_t)T_AL : (uint32_t)T_AH;
                const uint32_t boff = (split == 1) ? (uint32_t)T_BL : (uint32_t)T_BH;
                uint32_t a[4][4], b[2][4];
                #pragma unroll
                for (int mt = 0; mt < 4; ++mt)
                    ldsm4(a[mt], st + aoff + (uint32_t)((wm + mt * 16 + mrow) * 80 + kb + ks * 32));
                #pragma unroll
                for (int np = 0; np < 2; ++np)
                    ldsm4(b[np], st + boff + (uint32_t)((wn + np * 16 + mrow) * 80 + kb + ks * 32));
                #pragma unroll
                for (int mt = 0; mt < 4; ++mt)
                    #pragma unroll
                    for (int nt = 0; nt < 4; ++nt)
                        mma16816(c[mt][nt], a[mt][0], a[mt][1], a[mt][2], a[mt][3],
                                 b[nt >> 1][nt & 1], b[nt >> 1][(nt & 1) + 2]);
            }
        }
        __syncthreads();
    }

    // Epilogue: rebuild q[m,f] tile in smem from qT hi+lo (coalesced), stride 132
    float* sq = (float*)sm;
    for (int u = t; u < 128 * 16; u += 256) {
        int row = u >> 4;          // f_local
        int un  = u & 15;          // 8-elem unit along m
        size_t g = (size_t)row * 1024 + (size_t)m0 * 2 + un * 16;
        uint4 h4 = *(const uint4*)(Bh + g);
        uint4 l4 = *(const uint4*)(Bl + g);
        float* dst = sq + row * 132 + un * 8;
        uint32_t hw[4] = {h4.x, h4.y, h4.z, h4.w};
        uint32_t lw[4] = {l4.x, l4.y, l4.z, l4.w};
        #pragma unroll
        for (int wi = 0; wi < 4; ++wi) {
            dst[wi * 2 + 0] = bf_lo(hw[wi]) + bf_lo(lw[wi]);
            dst[wi * 2 + 1] = bf_hi(hw[wi]) + bf_hi(lw[wi]);
        }
    }
    __syncthreads();

    float* outB = out + ((size_t)(s * N_ATOM) + m0) * F_DIM + f0;
    #pragma unroll
    for (int mt = 0; mt < 4; ++mt) {
        #pragma unroll
        for (int nt = 0; nt < 4; ++nt) {
            const int ml = wm + mt * 16 + (lane >> 2);
            const int fl = wn + nt * 8 + (lane & 3) * 2;
            float* cf = c[mt][nt];
            float q00 = sq[fl * 132 + ml], q01 = sq[(fl + 1) * 132 + ml];
            float2 o0 = make_float2(0.5f * cf[0] * q00, 0.5f * cf[1] * q01);
            *(float2*)(outB + (size_t)ml * F_DIM + fl) = o0;
            float q10 = sq[fl * 132 + ml + 8], q11 = sq[(fl + 1) * 132 + ml + 8];
            float2 o1 = make_float2(0.5f * cf[2] * q10, 0.5f * cf[3] * q11);
            *(float2*)(outB + (size_t)(ml + 8) * F_DIM + fl) = o1;
        }
    }
}

// ---------------------------------------------------------------------------
// GEMM1: qT[s][f][a] = sum_k W[f,k] feat[a,k] + b[f], written as bf16 hi/lo.
// M=f (grid.y: 2 tiles), N=atoms (grid.x: 128 tiles), K=256. fp32->bf16 split
// happens in the tile loader (single smem stage, sync pipeline).
// ---------------------------------------------------------------------------
__global__ __launch_bounds__(256, 2) void gemm1_mma(
    const float* __restrict__ W, const float* __restrict__ feat,
    const float* __restrict__ bias,
    uint16_t* __restrict__ qhi, uint16_t* __restrict__ qlo)
{
    extern __shared__ char sm[];
    const int t = threadIdx.x, lane = t & 31, w = t >> 5;
    const int wm = (w & 1) * 64, wn = (w >> 1) * 32;
    const int fB = blockIdx.y * 128, aB = blockIdx.x * 128;
    const uint32_t sb = smem_u32(sm);

    const float* Ab = W + (size_t)fB * F_DIM;
    const float* Bb = feat + (size_t)aB * F_DIM;

    float c[4][4][4] = {};
    const int mrow = (lane & 7) + ((lane >> 3) & 1) * 8;
    const int kb   = (lane >> 4) * 16;

    for (int ch = 0; ch < 8; ++ch) {
        // load + split fp32 -> bf16 hi/lo into smem
        #pragma unroll
        for (int half = 0; half < 2; ++half) {
            const float* src = half ? Bb : Ab;
            const uint32_t basehi = half ? (uint32_t)T_BH : (uint32_t)T_AH;
            #pragma unroll
            for (int j = 0; j < 4; ++j) {
                int u = t + j * 256;
                int row = u >> 3, kq = u & 7;
                float4 x = *(const float4*)(src + (size_t)row * F_DIM + ch * 32 + kq * 4);
                uint32_t h01 = pack_bf16(x.x, x.y);
                uint32_t h23 = pack_bf16(x.z, x.w);
                uint32_t l01 = pack_bf16(x.x - bf_lo(h01), x.y - bf_hi(h01));
                uint32_t l23 = pack_bf16(x.z - bf_lo(h23), x.w - bf_hi(h23));
                uint32_t off = (uint32_t)(row * 80 + kq * 8);
                *(uint2*)(sm + basehi + off)         = make_uint2(h01, h23);
                *(uint2*)(sm + basehi + 10240 + off) = make_uint2(l01, l23);
            }
        }
        __syncthreads();

        #pragma unroll
        for (int ks = 0; ks < 2; ++ks) {
            #pragma unroll
            for (int split = 0; split < 3; ++split) {
                const uint32_t aoff = (split == 2) ? (uint32_t)T_AL : (uint32_t)T_AH;
                const uint32_t boff = (split == 1) ? (uint32_t)T_BL : (uint32_t)T_BH;
                uint32_t a[4][4], b[2][4];
                #pragma unroll
                for (int mt = 0; mt < 4; ++mt)
                    ldsm4(a[mt], sb + aoff + (uint32_t)((wm + mt * 16 + mrow) * 80 + kb + ks * 32));
                #pragma unroll
                for (int np = 0; np < 2; ++np)
                    ldsm4(b[np], sb + boff + (uint32_t)((wn + np * 16 + mrow) * 80 + kb + ks * 32));
                #pragma unroll
                for (int mt = 0; mt < 4; ++mt)
                    #pragma unroll
                    for (int nt = 0; nt < 4; ++nt)
                        mma16816(c[mt][nt], a[mt][0], a[mt][1], a[mt][2], a[mt][3],
                                 b[nt >> 1][nt & 1], b[nt >> 1][(nt & 1) + 2]);
            }
        }
        __syncthreads();
    }

    // epilogue: add bias, split to bf16 hi/lo, store qT[s][f][a]
    const int sID = aB >> 9;
    const int aLoc = aB & 511;
    uint16_t* qh = qhi + (size_t)sID * F_DIM * N_ATOM;
    uint16_t* ql = qlo + (size_t)sID * F_DIM * N_ATOM;
    #pragma unroll
    for (int mt = 0; mt < 4; ++mt) {
        #pragma unroll
        for (int nt = 0; nt < 4; ++nt) {
            const int fg = fB + wm + mt * 16 + (lane >> 2);
            const int ag = aLoc + wn + nt * 8 + (lane & 3) * 2;
            float* cf = c[mt][nt];
            float bv0 = bias[fg], bv1 = bias[fg + 8];
            float y0 = cf[0] + bv0, y1 = cf[1] + bv0;
            float y2 = cf[2] + bv1, y3 = cf[3] + bv1;
            uint32_t h01 = pack_bf16(y0, y1);
            uint32_t l01 = pack_bf16(y0 - bf_lo(h01), y1 - bf_hi(h01));
            *(uint32_t*)(qh + (size_t)fg * N_ATOM + ag) = h01;
            *(uint32_t*)(ql + (size_t)fg * N_ATOM + ag) = l01;
            uint32_t h23 = pack_bf16(y2, y3);
            uint32_t l23 = pack_bf16(y2 - bf_lo(h23), y3 - bf_hi(h23));
            *(uint32_t*)(qh + (size_t)(fg + 8) * N_ATOM + ag) = h23;
            *(uint32_t*)(ql + (size_t)(fg + 8) * N_ATOM + ag) = l23;
        }
    }
}

// ---------------------------------------------------------------------------
// Pair potential -> bf16 hi/lo. One block per (8 i-rows, system).
// ---------------------------------------------------------------------------
__global__ __launch_bounds__(256) void pair_kernel(
    const float* __restrict__ pos, uint16_t* __restrict__ vhi, uint16_t* __restrict__ vlo)
{
    __shared__ float sx[N_ATOM], sy[N_ATOM], sz[N_ATOM];
    const int s = blockIdx.y;
    const int i0 = blockIdx.x * 8;
    const float* ps = pos + (size_t)s * N_ATOM * 3;
    const int t = threadIdx.x;
    for (int j = t; j < N_ATOM; j += 256) {
        sx[j] = ps[j * 3 + 0];
        sy[j] = ps[j * 3 + 1];
        sz[j] = ps[j * 3 + 2];
    }
    __syncthreads();
    const int r = t >> 5, lid = t & 31;
    const int i = i0 + r;
    const float xi = sx[i], yi = sy[i], zi = sz[i];
    uint16_t* rh = vhi + ((size_t)s * N_ATOM + i) * N_ATOM;
    uint16_t* rl = vlo + ((size_t)s * N_ATOM + i) * N_ATOM;
    const float cc = 3.14159265358979323846f / R_EXCL;
    for (int jq = lid; jq < 128; jq += 32) {
        float val[4];
        #pragma unroll
        for (int e = 0; e < 4; ++e) {
            int j = jq * 4 + e;
            float dx = xi - sx[j], dy = yi - sy[j], dz = zi - sz[j];
            float d2 = fmaf(dx, dx, fmaf(dy, dy, dz * dz));
            float v = 0.0f;
            if (j != i) {
                float inv = rsqrtf(d2);
                float d = d2 * inv;
                float fcut = (d < R_EXCL) ? 0.5f * (1.0f + cosf(cc * d)) : 0.0f;
                v = (1.0f - fcut) * inv;
            }
            val[e] = v;
        }
        uint32_t h01 = pack_bf16(val[0], val[1]);
        uint32_t h23 = pack_bf16(val[2], val[3]);
        uint32_t l01 = pack_bf16(val[0] - bf_lo(h01), val[1] - bf_hi(h01));
        uint32_t l23 = pack_bf16(val[2] - bf_lo(h23), val[3] - bf_hi(h23));
        *(uint2*)(rh + jq * 4) = make_uint2(h01, h23);
        *(uint2*)(rl + jq * 4) = make_uint2(l01, l23);
    }
}

// ---------------------------------------------------------------------------
extern "C" void kernel_launch(void* const* d_in, const int* in_sizes, int n_in,
                              void* d_out, int out_size)
{
    const float* positions = (const float*)d_in[0]; // [32, 512, 3]
    const float* features  = (const float*)d_in[1]; // [16384, 256]
    const float* W         = (const float*)d_in[2]; // [256, 256]
    const float* b         = (const float*)d_in[3]; // [256]
    float* out             = (float*)d_out;         // [16384, 256]

    uint16_t *vhi, *vlo, *qhi, *qlo;
    cudaGetSymbolAddress((void**)&vhi, g_vhi);
    cudaGetSymbolAddress((void**)&vlo, g_vlo);
    cudaGetSymbolAddress((void**)&qhi, g_qhi);
    cudaGetSymbolAddress((void**)&qlo, g_qlo);

    cudaFuncSetAttribute(gemm1_mma, cudaFuncAttributeMaxDynamicSharedMemorySize, STAGE);
    cudaFuncSetAttribute(gemm2_mma, cudaFuncAttributeMaxDynamicSharedMemorySize, 2 * STAGE);

    // q^T (hi/lo bf16) = W @ feat^T + b
    gemm1_mma<<<dim3(128, 2), 256, STAGE>>>(W, features, b, qhi, qlo);
    // pair matrices (hi/lo bf16)
    pair_kernel<<<dim3(N_ATOM / 8, S_SYS), 256>>>(positions, vhi, vlo);
    // out = 0.5 * (v @ q) * q
    gemm2_mma<<<dim3(2, 4, 32), 256, 2 * STAGE>>>(vhi, vlo, qhi, qlo, out);
}

// round 7
// speedup vs baseline: 2.2393x; 1.0203x over previous
#include <cuda_runtime.h>
#include <cuda_bf16.h>
#include <cstdint>
#include <math.h>

#define S_SYS 32
#define N_ATOM 512
#define F_DIM 256
#define R_EXCL 5.0f

// Scratch (__device__ globals; allocation-free rule). bf16 stored as uint16.
__device__ __align__(16) uint16_t g_qhi[(size_t)S_SYS * F_DIM * N_ATOM];  // 8 MB (q^T hi)
__device__ __align__(16) uint16_t g_qlo[(size_t)S_SYS * F_DIM * N_ATOM];  // 8 MB (q^T lo)

// ---------------------------------------------------------------------------
// helpers
// ---------------------------------------------------------------------------
__device__ __forceinline__ uint32_t smem_u32(const void* p) {
    uint32_t a;
    asm("{ .reg .u64 t; cvta.to.shared.u64 t, %1; cvt.u32.u64 %0, t; }" : "=r"(a) : "l"(p));
    return a;
}
// pack two floats to bf16x2, first arg in LOW half
__device__ __forceinline__ uint32_t pack_bf16(float lo_elem, float hi_elem) {
    uint32_t r;
    asm("cvt.rn.bf16x2.f32 %0, %1, %2;" : "=r"(r) : "f"(hi_elem), "f"(lo_elem));
    return r;
}
__device__ __forceinline__ float bf_lo(uint32_t p) { return __uint_as_float(p << 16); }
__device__ __forceinline__ float bf_hi(uint32_t p) { return __uint_as_float(p & 0xFFFF0000u); }

__device__ __forceinline__ void mma16816(float* c, uint32_t a0, uint32_t a1, uint32_t a2,
                                         uint32_t a3, uint32_t b0, uint32_t b1) {
    asm volatile(
        "mma.sync.aligned.m16n8k16.row.col.f32.bf16.bf16.f32 "
        "{%0,%1,%2,%3}, {%4,%5,%6,%7}, {%8,%9}, {%0,%1,%2,%3};"
        : "+f"(c[0]), "+f"(c[1]), "+f"(c[2]), "+f"(c[3])
        : "r"(a0), "r"(a1), "r"(a2), "r"(a3), "r"(b0), "r"(b1));
}
__device__ __forceinline__ void ldsm4(uint32_t* r, uint32_t addr) {
    asm volatile("ldmatrix.sync.aligned.m8n8.x4.shared.b16 {%0,%1,%2,%3}, [%4];"
                 : "=r"(r[0]), "=r"(r[1]), "=r"(r[2]), "=r"(r[3]) : "r"(addr));
}
#define CP_ASYNC16(dst, src) \
    asm volatile("cp.async.cg.shared.global [%0], [%1], 16;" :: "r"(dst), "l"(src))
#define CP_COMMIT() asm volatile("cp.async.commit_group;" ::: "memory")
#define CP_WAIT(n)  asm volatile("cp.async.wait_group %0;" :: "n"(n) : "memory")

// ---------------------------------------------------------------------------
// Shared MMA engine: 3-split bf16 (AH*BH + AH*BL + AL*BH), frag reuse.
// bf16 tiles: 128 rows x 64B (32 bf16), 80B row stride.
// ---------------------------------------------------------------------------
__device__ __forceinline__ void mma_step(
    uint32_t aH, uint32_t aL, uint32_t bH, uint32_t bL,
    int wm, int wn, int mrow, int kb, float c[4][4][4])
{
    #pragma unroll
    for (int ks = 0; ks < 2; ++ks) {
        const uint32_t col = (uint32_t)(kb + ks * 32);
        uint32_t ah[4][4], bh[2][4], bl[2][4];
        #pragma unroll
        for (int mt = 0; mt < 4; ++mt)
            ldsm4(ah[mt], aH + (uint32_t)((wm + mt * 16 + mrow) * 80) + col);
        #pragma unroll
        for (int np = 0; np < 2; ++np)
            ldsm4(bh[np], bH + (uint32_t)((wn + np * 16 + mrow) * 80) + col);
        #pragma unroll
        for (int np = 0; np < 2; ++np)
            ldsm4(bl[np], bL + (uint32_t)((wn + np * 16 + mrow) * 80) + col);
        #pragma unroll
        for (int mt = 0; mt < 4; ++mt)
            #pragma unroll
            for (int nt = 0; nt < 4; ++nt)
                mma16816(c[mt][nt], ah[mt][0], ah[mt][1], ah[mt][2], ah[mt][3],
                         bh[nt >> 1][nt & 1], bh[nt >> 1][(nt & 1) + 2]);
        #pragma unroll
        for (int mt = 0; mt < 4; ++mt)
            #pragma unroll
            for (int nt = 0; nt < 4; ++nt)
                mma16816(c[mt][nt], ah[mt][0], ah[mt][1], ah[mt][2], ah[mt][3],
                         bl[nt >> 1][nt & 1], bl[nt >> 1][(nt & 1) + 2]);
        uint32_t al[4][4];
        #pragma unroll
        for (int mt = 0; mt < 4; ++mt)
            ldsm4(al[mt], aL + (uint32_t)((wm + mt * 16 + mrow) * 80) + col);
        #pragma unroll
        for (int mt = 0; mt < 4; ++mt)
            #pragma unroll
            for (int nt = 0; nt < 4; ++nt)
                mma16816(c[mt][nt], al[mt][0], al[mt][1], al[mt][2], al[mt][3],
                         bh[nt >> 1][nt & 1], bh[nt >> 1][(nt & 1) + 2]);
    }
}

// ---------------------------------------------------------------------------
// GEMM1: qT[s][f][a] = sum_k W[f,k]*feat[a,k] + b[f]  (bf16 hi/lo out)
// cp.async double-buffered raw fp32 stages + in-smem bf16 split.
// smem: raw stage0 @0 (A 16K, B 16K), stage1 @32768; bf16 tiles @65536.
// ---------------------------------------------------------------------------
#define G1_RAW(st)  ((st) * 32768)
#define G1_AH 65536
#define G1_AL 75776
#define G1_BH 86016
#define G1_BL 96256
#define G1_SMEM 106496

__global__ __launch_bounds__(256, 2) void gemm1_mma(
    const float* __restrict__ W, const float* __restrict__ feat,
    const float* __restrict__ bias,
    uint16_t* __restrict__ qhi, uint16_t* __restrict__ qlo)
{
    extern __shared__ char sm[];
    const int t = threadIdx.x, lane = t & 31, w = t >> 5;
    const int wm = (w & 1) * 64, wn = (w >> 1) * 32;
    const int aB = blockIdx.x * 128, fB = blockIdx.y * 128;
    const uint32_t sb = smem_u32(sm);

    const char* Ag = (const char*)(W + (size_t)fB * F_DIM);     // row stride 1024B
    const char* Bg = (const char*)(feat + (size_t)aB * F_DIM);  // row stride 1024B

    float c[4][4][4] = {};
    const int mrow = (lane & 7) + ((lane >> 3) & 1) * 8;
    const int kb   = (lane >> 4) * 16;

    // prefetch raw chunk 0
    {
        #pragma unroll
        for (int j = 0; j < 8; ++j) {
            int u = t + j * 256;
            int op = u >> 10, s2 = u & 1023, row = s2 >> 3, sg = s2 & 7;
            const char* src = (op ? Bg : Ag) + (size_t)row * 1024 + sg * 16;
            CP_ASYNC16(sb + G1_RAW(0) + (uint32_t)(op * 16384 + row * 128 + sg * 16), src);
        }
        CP_COMMIT();
    }

    for (int ch = 0; ch < 8; ++ch) {
        if (ch + 1 < 8) {
            const uint32_t st = sb + G1_RAW((ch + 1) & 1);
            #pragma unroll
            for (int j = 0; j < 8; ++j) {
                int u = t + j * 256;
                int op = u >> 10, s2 = u & 1023, row = s2 >> 3, sg = s2 & 7;
                const char* src = (op ? Bg : Ag) + (size_t)row * 1024 + (ch + 1) * 128 + sg * 16;
                CP_ASYNC16(st + (uint32_t)(op * 16384 + row * 128 + sg * 16), src);
            }
            CP_COMMIT();
            CP_WAIT(1);
        } else {
            CP_WAIT(0);
        }
        __syncthreads();   // raw[ch] visible; bf16 tiles free (prev MMA done)

        // convert raw fp32 -> bf16 hi/lo tiles
        const char* raw = sm + G1_RAW(ch & 1);
        #pragma unroll
        for (int half = 0; half < 2; ++half) {
            const uint32_t th = half ? (uint32_t)G1_BH : (uint32_t)G1_AH;
            #pragma unroll
            for (int j = 0; j < 4; ++j) {
                int u = t + j * 256;
                int row = u >> 3, kq = u & 7;
                float4 x = *(const float4*)(raw + half * 16384 + row * 128 + kq * 16);
                uint32_t h01 = pack_bf16(x.x, x.y);
                uint32_t h23 = pack_bf16(x.z, x.w);
                uint32_t l01 = pack_bf16(x.x - bf_lo(h01), x.y - bf_hi(h01));
                uint32_t l23 = pack_bf16(x.z - bf_lo(h23), x.w - bf_hi(h23));
                uint32_t off = (uint32_t)(row * 80 + kq * 8);
                *(uint2*)(sm + th + off)         = make_uint2(h01, h23);
                *(uint2*)(sm + th + 10240 + off) = make_uint2(l01, l23);
            }
        }
        __syncthreads();

        mma_step(sb + G1_AH, sb + G1_AL, sb + G1_BH, sb + G1_BL, wm, wn, mrow, kb, c);
    }

    // epilogue: add bias, split to bf16 hi/lo, store qT[s][f][a]
    const int sID = aB >> 9;
    const int aLoc = aB & 511;
    uint16_t* qh = qhi + (size_t)sID * F_DIM * N_ATOM;
    uint16_t* ql = qlo + (size_t)sID * F_DIM * N_ATOM;
    #pragma unroll
    for (int mt = 0; mt < 4; ++mt) {
        #pragma unroll
        for (int nt = 0; nt < 4; ++nt) {
            const int fg = fB + wm + mt * 16 + (lane >> 2);
            const int ag = aLoc + wn + nt * 8 + (lane & 3) * 2;
            float* cf = c[mt][nt];
            float bv0 = bias[fg], bv1 = bias[fg + 8];
            float y0 = cf[0] + bv0, y1 = cf[1] + bv0;
            float y2 = cf[2] + bv1, y3 = cf[3] + bv1;
            uint32_t h01 = pack_bf16(y0, y1);
            uint32_t l01 = pack_bf16(y0 - bf_lo(h01), y1 - bf_hi(h01));
            *(uint32_t*)(qh + (size_t)fg * N_ATOM + ag) = h01;
            *(uint32_t*)(ql + (size_t)fg * N_ATOM + ag) = l01;
            uint32_t h23 = pack_bf16(y2, y3);
            uint32_t l23 = pack_bf16(y2 - bf_lo(h23), y3 - bf_hi(h23));
            *(uint32_t*)(qh + (size_t)(fg + 8) * N_ATOM + ag) = h23;
            *(uint32_t*)(ql + (size_t)(fg + 8) * N_ATOM + ag) = l23;
        }
    }
}

// ---------------------------------------------------------------------------
// GEMM2 fused: v-tiles computed on the fly from positions (no v in DRAM).
// out[s,m,f] = 0.5 * (sum_j v(m,j) q[j,f]) * q[m,f]
// smem: pos sx@0 sy@2048 sz@4096 | VH@6144 VL@16384 | q stages @26624 (2x20480)
// ---------------------------------------------------------------------------
#define G2_SX 0
#define G2_SY 2048
#define G2_SZ 4096
#define G2_VH 6144
#define G2_VL 16384
#define G2_QS(st) (26624 + (st) * 20480)   // QH at +0, QL at +10240
#define G2_SMEM 69632

__global__ __launch_bounds__(256, 2) void gemm2_fused(
    const float* __restrict__ pos,
    const uint16_t* __restrict__ qhi, const uint16_t* __restrict__ qlo,
    float* __restrict__ out)
{
    extern __shared__ char sm[];
    const int t = threadIdx.x, lane = t & 31, w = t >> 5;
    const int wm = (w & 1) * 64, wn = (w >> 1) * 32;
    const int s = blockIdx.z, m0 = blockIdx.y * 128, f0 = blockIdx.x * 128;
    const uint32_t sb = smem_u32(sm);

    float* sx = (float*)(sm + G2_SX);
    float* sy = (float*)(sm + G2_SY);
    float* sz = (float*)(sm + G2_SZ);

    // stage all positions of system s
    const float* ps = pos + (size_t)s * N_ATOM * 3;
    for (int j = t; j < N_ATOM; j += 256) {
        sx[j] = ps[j * 3 + 0];
        sy[j] = ps[j * 3 + 1];
        sz[j] = ps[j * 3 + 2];
    }
    __syncthreads();

    const int irow = t >> 1;                 // 0..127 (this thread's v row)
    const int jh   = (t & 1) * 16;           // j-half within 32-chunk
    const int ig   = m0 + irow;              // global i index
    const float xi = sx[ig], yi = sy[ig], zi = sz[ig];
    const float cc = 3.14159265358979323846f / R_EXCL;

    const char* Bh = (const char*)(qhi + ((size_t)s * F_DIM + f0) * N_ATOM);
    const char* Bl = (const char*)(qlo + ((size_t)s * F_DIM + f0) * N_ATOM);
    // q row stride = 512 bf16 = 1024 B

    float c[4][4][4] = {};
    const int mrow = (lane & 7) + ((lane >> 3) & 1) * 8;
    const int kb   = (lane >> 4) * 16;

    // prefetch q chunk 0
    {
        #pragma unroll
        for (int j = 0; j < 4; ++j) {
            int u = t + j * 256;
            int tl = u >> 9, s2 = u & 511, row = s2 >> 2, c16 = s2 & 3;
            const char* src = (tl ? Bl : Bh) + (size_t)row * 1024 + c16 * 16;
            CP_ASYNC16(sb + (uint32_t)(G2_QS(0) + tl * 10240 + row * 80 + c16 * 16), src);
        }
        CP_COMMIT();
    }

    for (int ch = 0; ch < 16; ++ch) {
        if (ch + 1 < 16) {
            const uint32_t st = sb + (uint32_t)G2_QS((ch + 1) & 1);
            #pragma unroll
            for (int j = 0; j < 4; ++j) {
                int u = t + j * 256;
                int tl = u >> 9, s2 = u & 511, row = s2 >> 2, c16 = s2 & 3;
                const char* src = (tl ? Bl : Bh) + (size_t)row * 1024 + (ch + 1) * 64 + c16 * 16;
                CP_ASYNC16(st + (uint32_t)(tl * 10240 + row * 80 + c16 * 16), src);
            }
            CP_COMMIT();
        }

        // compute v chunk ch: 16 j's per thread, in two halves of 8
        {
            const int jbase = ch * 32 + jh;
            #pragma unroll
            for (int half = 0; half < 2; ++half) {
                float v[8];
                #pragma unroll
                for (int e = 0; e < 8; ++e) {
                    int j = jbase + half * 8 + e;
                    float dx = xi - sx[j], dy = yi - sy[j], dz = zi - sz[j];
                    float d2 = fmaf(dx, dx, fmaf(dy, dy, dz * dz));
                    float val = 0.0f;
                    if (j != ig) {
                        float inv = rsqrtf(d2);
                        float d = d2 * inv;
                        float fcut = (d < R_EXCL) ? 0.5f * (1.0f + __cosf(cc * d)) : 0.0f;
                        val = (1.0f - fcut) * inv;
                    }
                    v[e] = val;
                }
                uint4 ph, pl;
                uint32_t* hw = (uint32_t*)&ph;
                uint32_t* lw = (uint32_t*)&pl;
                #pragma unroll
                for (int p = 0; p < 4; ++p) {
                    uint32_t h = pack_bf16(v[2 * p], v[2 * p + 1]);
                    hw[p] = h;
                    lw[p] = pack_bf16(v[2 * p] - bf_lo(h), v[2 * p + 1] - bf_hi(h));
                }
                uint32_t off = (uint32_t)(irow * 80 + jh * 2 + half * 16);
                *(uint4*)(sm + G2_VH + off) = ph;
                *(uint4*)(sm + G2_VL + off) = pl;
            }
        }

        if (ch + 1 < 16) CP_WAIT(1); else CP_WAIT(0);
        __syncthreads();   // v visible, q[ch] ready, prev MMA done via trailing sync

        const uint32_t qs = sb + (uint32_t)G2_QS(ch & 1);
        mma_step(sb + G2_VH, sb + G2_VL, qs, qs + 10240, wm, wn, mrow, kb, c);
        __syncthreads();   // protect VH/VL and q stage before overwrite
    }

    // Epilogue: rebuild q[m,f] tile in smem (stride 132), then out = 0.5*D*q
    float* sq = (float*)sm;
    for (int u = t; u < 128 * 16; u += 256) {
        int row = u >> 4;          // f_local
        int un  = u & 15;          // 8-elem unit along m
        size_t g = (size_t)row * 1024 + (size_t)m0 * 2 + un * 16;
        uint4 h4 = *(const uint4*)(Bh + g);
        uint4 l4 = *(const uint4*)(Bl + g);
        float* dst = sq + row * 132 + un * 8;
        uint32_t hw[4] = {h4.x, h4.y, h4.z, h4.w};
        uint32_t lw[4] = {l4.x, l4.y, l4.z, l4.w};
        #pragma unroll
        for (int wi = 0; wi < 4; ++wi) {
            dst[wi * 2 + 0] = bf_lo(hw[wi]) + bf_lo(lw[wi]);
            dst[wi * 2 + 1] = bf_hi(hw[wi]) + bf_hi(lw[wi]);
        }
    }
    __syncthreads();

    float* outB = out + ((size_t)(s * N_ATOM) + m0) * F_DIM + f0;
    #pragma unroll
    for (int mt = 0; mt < 4; ++mt) {
        #pragma unroll
        for (int nt = 0; nt < 4; ++nt) {
            const int ml = wm + mt * 16 + (lane >> 2);
            const int fl = wn + nt * 8 + (lane & 3) * 2;
            float* cf = c[mt][nt];
            float q00 = sq[fl * 132 + ml], q01 = sq[(fl + 1) * 132 + ml];
            float2 o0 = make_float2(0.5f * cf[0] * q00, 0.5f * cf[1] * q01);
            *(float2*)(outB + (size_t)ml * F_DIM + fl) = o0;
            float q10 = sq[fl * 132 + ml + 8], q11 = sq[(fl + 1) * 132 + ml + 8];
            float2 o1 = make_float2(0.5f * cf[2] * q10, 0.5f * cf[3] * q11);
            *(float2*)(outB + (size_t)(ml + 8) * F_DIM + fl) = o1;
        }
    }
}

// ---------------------------------------------------------------------------
extern "C" void kernel_launch(void* const* d_in, const int* in_sizes, int n_in,
                              void* d_out, int out_size)
{
    const float* positions = (const float*)d_in[0]; // [32, 512, 3]
    const float* features  = (const float*)d_in[1]; // [16384, 256]
    const float* W         = (const float*)d_in[2]; // [256, 256]
    const float* b         = (const float*)d_in[3]; // [256]
    float* out             = (float*)d_out;         // [16384, 256]

    uint16_t *qhi, *qlo;
    cudaGetSymbolAddress((void**)&qhi, g_qhi);
    cudaGetSymbolAddress((void**)&qlo, g_qlo);

    cudaFuncSetAttribute(gemm1_mma, cudaFuncAttributeMaxDynamicSharedMemorySize, G1_SMEM);
    cudaFuncSetAttribute(gemm2_fused, cudaFuncAttributeMaxDynamicSharedMemorySize, G2_SMEM);

    // q^T (hi/lo bf16) = W @ feat^T + b
    gemm1_mma<<<dim3(128, 2), 256, G1_SMEM>>>(W, features, b, qhi, qlo);
    // out = 0.5 * (v @ q) * q, v generated in-kernel from positions
    gemm2_fused<<<dim3(2, 4, 32), 256, G2_SMEM>>>(positions, qhi, qlo, out);
}

// round 8
// speedup vs baseline: 2.5345x; 1.1318x over previous
#include <cuda_runtime.h>
#include <cuda_bf16.h>
#include <cstdint>
#include <math.h>

#define S_SYS 32
#define N_ATOM 512
#define F_DIM 256
#define R_EXCL 5.0f

// Scratch (__device__ globals; allocation-free rule). bf16 stored as uint16.
__device__ __align__(16) uint16_t g_qhi[(size_t)S_SYS * F_DIM * N_ATOM];  // 8 MB (q^T hi)
__device__ __align__(16) uint16_t g_qlo[(size_t)S_SYS * F_DIM * N_ATOM];  // 8 MB (q^T lo)

// ---------------------------------------------------------------------------
// helpers
// ---------------------------------------------------------------------------
__device__ __forceinline__ uint32_t smem_u32(const void* p) {
    uint32_t a;
    asm("{ .reg .u64 t; cvta.to.shared.u64 t, %1; cvt.u32.u64 %0, t; }" : "=r"(a) : "l"(p));
    return a;
}
// pack two floats to bf16x2, first arg in LOW half
__device__ __forceinline__ uint32_t pack_bf16(float lo_elem, float hi_elem) {
    uint32_t r;
    asm("cvt.rn.bf16x2.f32 %0, %1, %2;" : "=r"(r) : "f"(hi_elem), "f"(lo_elem));
    return r;
}
__device__ __forceinline__ float bf_lo(uint32_t p) { return __uint_as_float(p << 16); }
__device__ __forceinline__ float bf_hi(uint32_t p) { return __uint_as_float(p & 0xFFFF0000u); }

__device__ __forceinline__ void mma16816(float* c, const uint32_t* a, uint32_t b0, uint32_t b1) {
    asm volatile(
        "mma.sync.aligned.m16n8k16.row.col.f32.bf16.bf16.f32 "
        "{%0,%1,%2,%3}, {%4,%5,%6,%7}, {%8,%9}, {%0,%1,%2,%3};"
        : "+f"(c[0]), "+f"(c[1]), "+f"(c[2]), "+f"(c[3])
        : "r"(a[0]), "r"(a[1]), "r"(a[2]), "r"(a[3]), "r"(b0), "r"(b1));
}
__device__ __forceinline__ void ldsm4(uint32_t* r, uint32_t addr) {
    asm volatile("ldmatrix.sync.aligned.m8n8.x4.shared.b16 {%0,%1,%2,%3}, [%4];"
                 : "=r"(r[0]), "=r"(r[1]), "=r"(r[2]), "=r"(r[3]) : "r"(addr));
}
#define CP_ASYNC16(dst, src) \
    asm volatile("cp.async.cg.shared.global [%0], [%1], 16;" :: "r"(dst), "l"(src))
#define CP_COMMIT() asm volatile("cp.async.commit_group;" ::: "memory")
#define CP_WAIT(n)  asm volatile("cp.async.wait_group %0;" :: "n"(n) : "memory")

// ===========================================================================
// GEMM1: qT[s][f][a] = sum_k W[f,k]*feat[a,k] + b[f]  (bf16 hi/lo out)
// BM(f)=256, BN(atom)=128, BK=32, 512 threads, warp tile 64x32 (4x4 warps).
// cp.async double-buffered raw fp32 stages + in-smem bf16 split.
// ===========================================================================
#define G1_RAWA(st) ((st) * 49152)
#define G1_RAWB(st) ((st) * 49152 + 32768)
#define G1_AH 98304
#define G1_AL 118784
#define G1_BH 139264
#define G1_BL 149504
#define G1_SMEM 159744

__device__ __forceinline__ void gemm1_step(
    uint32_t sb, const uint32_t arow[4], const uint32_t brow[2], float c[4][4][4])
{
    #pragma unroll
    for (int ks = 0; ks < 2; ++ks) {
        const uint32_t col = (uint32_t)(ks * 32);
        uint32_t ah[4][4], al[4][4], bh[2][4];
        #pragma unroll
        for (int mt = 0; mt < 4; ++mt) ldsm4(ah[mt], sb + G1_AH + arow[mt] + col);
        #pragma unroll
        for (int mt = 0; mt < 4; ++mt) ldsm4(al[mt], sb + G1_AL + arow[mt] + col);
        #pragma unroll
        for (int np = 0; np < 2; ++np) ldsm4(bh[np], sb + G1_BH + brow[np] + col);
        #pragma unroll
        for (int mt = 0; mt < 4; ++mt)
            #pragma unroll
            for (int nt = 0; nt < 4; ++nt)
                mma16816(c[mt][nt], ah[mt], bh[nt >> 1][nt & 1], bh[nt >> 1][(nt & 1) + 2]);
        #pragma unroll
        for (int mt = 0; mt < 4; ++mt)
            #pragma unroll
            for (int nt = 0; nt < 4; ++nt)
                mma16816(c[mt][nt], al[mt], bh[nt >> 1][nt & 1], bh[nt >> 1][(nt & 1) + 2]);
        uint32_t bl[2][4];
        #pragma unroll
        for (int np = 0; np < 2; ++np) ldsm4(bl[np], sb + G1_BL + brow[np] + col);
        #pragma unroll
        for (int mt = 0; mt < 4; ++mt)
            #pragma unroll
            for (int nt = 0; nt < 4; ++nt)
                mma16816(c[mt][nt], ah[mt], bl[nt >> 1][nt & 1], bl[nt >> 1][(nt & 1) + 2]);
    }
}

__global__ __launch_bounds__(512) void gemm1_mma(
    const float* __restrict__ W, const float* __restrict__ feat,
    const float* __restrict__ bias,
    uint16_t* __restrict__ qhi, uint16_t* __restrict__ qlo)
{
    extern __shared__ char sm[];
    const int t = threadIdx.x, lane = t & 31, w = t >> 5;
    const int wm = (w & 3) * 64, wn = (w >> 2) * 32;
    const int aB = blockIdx.x * 128;
    const uint32_t sb = smem_u32(sm);

    const char* Ag = (const char*)W;                            // 256 rows, 1024B stride
    const char* Bg = (const char*)(feat + (size_t)aB * F_DIM);  // 128 rows, 1024B stride

    float c[4][4][4] = {};
    const int mrow = (lane & 7) + ((lane >> 3) & 1) * 8;
    const int kb   = (lane >> 4) * 16;
    uint32_t arow[4], brow[2];
    #pragma unroll
    for (int mt = 0; mt < 4; ++mt) arow[mt] = (uint32_t)((wm + mt * 16 + mrow) * 80 + kb);
    #pragma unroll
    for (int np = 0; np < 2; ++np) brow[np] = (uint32_t)((wn + np * 16 + mrow) * 80 + kb);

    // raw loader mapping: 3072 float4/chunk, 6 per thread (j<4 -> A, j>=4 -> B)
    // prefetch raw chunk 0
    {
        #pragma unroll
        for (int j = 0; j < 6; ++j) {
            int u = t + j * 512;
            if (u < 2048) {
                int row = u >> 3, sg = u & 7;
                CP_ASYNC16(sb + G1_RAWA(0) + (uint32_t)(row * 128 + sg * 16),
                           Ag + (size_t)row * 1024 + sg * 16);
            } else {
                int u2 = u - 2048, row = u2 >> 3, sg = u2 & 7;
                CP_ASYNC16(sb + G1_RAWB(0) + (uint32_t)(row * 128 + sg * 16),
                           Bg + (size_t)row * 1024 + sg * 16);
            }
        }
        CP_COMMIT();
    }

    for (int ch = 0; ch < 8; ++ch) {
        if (ch + 1 < 8) {
            const int st = (ch + 1) & 1;
            #pragma unroll
            for (int j = 0; j < 6; ++j) {
                int u = t + j * 512;
                if (u < 2048) {
                    int row = u >> 3, sg = u & 7;
                    CP_ASYNC16(sb + G1_RAWA(st) + (uint32_t)(row * 128 + sg * 16),
                               Ag + (size_t)row * 1024 + (ch + 1) * 128 + sg * 16);
                } else {
                    int u2 = u - 2048, row = u2 >> 3, sg = u2 & 7;
                    CP_ASYNC16(sb + G1_RAWB(st) + (uint32_t)(row * 128 + sg * 16),
                               Bg + (size_t)row * 1024 + (ch + 1) * 128 + sg * 16);
                }
            }
            CP_COMMIT();
            CP_WAIT(1);
        } else {
            CP_WAIT(0);
        }
        __syncthreads();   // raw[ch] visible; bf16 tiles free (prev MMA done)

        // convert raw fp32 -> bf16 hi/lo tiles (6 float4 per thread)
        {
            const char* rawA = sm + G1_RAWA(ch & 1);
            const char* rawB = sm + G1_RAWB(ch & 1);
            #pragma unroll
            for (int j = 0; j < 6; ++j) {
                int u = t + j * 512;
                const char* src;
                uint32_t dhi, dlo;
                int row, kq;
                if (u < 2048) {
                    row = u >> 3; kq = u & 7;
                    src = rawA + row * 128 + kq * 16;
                    dhi = (uint32_t)G1_AH; dlo = (uint32_t)G1_AL;
                } else {
                    int u2 = u - 2048; row = u2 >> 3; kq = u2 & 7;
                    src = rawB + row * 128 + kq * 16;
                    dhi = (uint32_t)G1_BH; dlo = (uint32_t)G1_BL;
                }
                float4 x = *(const float4*)src;
                uint32_t h01 = pack_bf16(x.x, x.y);
                uint32_t h23 = pack_bf16(x.z, x.w);
                uint32_t l01 = pack_bf16(x.x - bf_lo(h01), x.y - bf_hi(h01));
                uint32_t l23 = pack_bf16(x.z - bf_lo(h23), x.w - bf_hi(h23));
                uint32_t off = (uint32_t)(row * 80 + kq * 8);
                *(uint2*)(sm + dhi + off) = make_uint2(h01, h23);
                *(uint2*)(sm + dlo + off) = make_uint2(l01, l23);
            }
        }
        __syncthreads();

        gemm1_step(sb, arow, brow, c);
    }

    // epilogue: add bias, split to bf16 hi/lo, store qT[s][f][a]
    const int sID = blockIdx.x >> 2;
    const int aLoc0 = (blockIdx.x & 3) * 128;
    uint16_t* qh = qhi + (size_t)sID * F_DIM * N_ATOM;
    uint16_t* ql = qlo + (size_t)sID * F_DIM * N_ATOM;
    #pragma unroll
    for (int mt = 0; mt < 4; ++mt) {
        #pragma unroll
        for (int nt = 0; nt < 4; ++nt) {
            const int fg = wm + mt * 16 + (lane >> 2);
            const int ag = aLoc0 + wn + nt * 8 + (lane & 3) * 2;
            float* cf = c[mt][nt];
            float bv0 = bias[fg], bv1 = bias[fg + 8];
            float y0 = cf[0] + bv0, y1 = cf[1] + bv0;
            float y2 = cf[2] + bv1, y3 = cf[3] + bv1;
            uint32_t h01 = pack_bf16(y0, y1);
            uint32_t l01 = pack_bf16(y0 - bf_lo(h01), y1 - bf_hi(h01));
            *(uint32_t*)(qh + (size_t)fg * N_ATOM + ag) = h01;
            *(uint32_t*)(ql + (size_t)fg * N_ATOM + ag) = l01;
            uint32_t h23 = pack_bf16(y2, y3);
            uint32_t l23 = pack_bf16(y2 - bf_lo(h23), y3 - bf_hi(h23));
            *(uint32_t*)(qh + (size_t)(fg + 8) * N_ATOM + ag) = h23;
            *(uint32_t*)(ql + (size_t)(fg + 8) * N_ATOM + ag) = l23;
        }
    }
}

// ===========================================================================
// GEMM2 fused: out[s,m,f] = 0.5 * (sum_j v(m,j) q[j,f]) * q[m,f]
// BM=128, BN=256 (all f), BK=32. 512 threads, warp tile 32x64 (4m x 4n warps).
// v computed on the fly; V and q both double-buffered -> 1 sync per chunk.
// smem: pos@0(6K) | V stages @6144 (2x20480) | Q stages @47104 (2x40960)
// ===========================================================================
#define G2_VS(st) (6144 + (st) * 20480)    // VH +0, VL +10240
#define G2_QS(st) (47104 + (st) * 40960)   // QH +0, QL +20480
#define G2_SMEM 129024

__device__ __forceinline__ void gemm2_step(
    uint32_t vbase, uint32_t qbase,
    const uint32_t arow[2], const uint32_t brow[4], float c[2][8][4])
{
    #pragma unroll
    for (int ks = 0; ks < 2; ++ks) {
        const uint32_t col = (uint32_t)(ks * 32);
        uint32_t ah[2][4], al[2][4], bh[4][4];
        #pragma unroll
        for (int mt = 0; mt < 2; ++mt) ldsm4(ah[mt], vbase + arow[mt] + col);
        #pragma unroll
        for (int mt = 0; mt < 2; ++mt) ldsm4(al[mt], vbase + 10240 + arow[mt] + col);
        #pragma unroll
        for (int np = 0; np < 4; ++np) ldsm4(bh[np], qbase + brow[np] + col);
        #pragma unroll
        for (int mt = 0; mt < 2; ++mt)
            #pragma unroll
            for (int nt = 0; nt < 8; ++nt)
                mma16816(c[mt][nt], ah[mt], bh[nt >> 1][nt & 1], bh[nt >> 1][(nt & 1) + 2]);
        #pragma unroll
        for (int mt = 0; mt < 2; ++mt)
            #pragma unroll
            for (int nt = 0; nt < 8; ++nt)
                mma16816(c[mt][nt], al[mt], bh[nt >> 1][nt & 1], bh[nt >> 1][(nt & 1) + 2]);
        uint32_t bl[4][4];
        #pragma unroll
        for (int np = 0; np < 4; ++np) ldsm4(bl[np], qbase + 20480 + brow[np] + col);
        #pragma unroll
        for (int mt = 0; mt < 2; ++mt)
            #pragma unroll
            for (int nt = 0; nt < 8; ++nt)
                mma16816(c[mt][nt], ah[mt], bl[nt >> 1][nt & 1], bl[nt >> 1][(nt & 1) + 2]);
    }
}

__global__ __launch_bounds__(512) void gemm2_fused(
    const float* __restrict__ pos,
    const uint16_t* __restrict__ qhi, const uint16_t* __restrict__ qlo,
    float* __restrict__ out)
{
    extern __shared__ char sm[];
    const int t = threadIdx.x, lane = t & 31, w = t >> 5;
    const int wm = (w & 3) * 32, wn = (w >> 2) * 64;
    const int m0 = blockIdx.x * 128, s = blockIdx.y;
    const uint32_t sb = smem_u32(sm);

    float* sx = (float*)(sm);
    float* sy = (float*)(sm + 2048);
    float* sz = (float*)(sm + 4096);

    // stage all positions of system s (512 threads -> 1 atom each)
    const float* ps = pos + (size_t)s * N_ATOM * 3;
    {
        float3 p = *(const float3*)(ps + t * 3);
        sx[t] = p.x; sy[t] = p.y; sz[t] = p.z;
    }
    __syncthreads();

    const int irow = t >> 2;            // 0..127 (v row)
    const int jq   = (t & 3);           // 8-j group within 32-chunk
    const int ig   = m0 + irow;
    const float xi = sx[ig], yi = sy[ig], zi = sz[ig];
    const float cc = 3.14159265358979323846f / R_EXCL;

    const char* Bh = (const char*)(qhi + (size_t)s * F_DIM * N_ATOM);  // 1024B row stride
    const char* Bl = (const char*)(qlo + (size_t)s * F_DIM * N_ATOM);

    float c[2][8][4] = {};
    const int mrow = (lane & 7) + ((lane >> 3) & 1) * 8;
    const int kb   = (lane >> 4) * 16;
    uint32_t arow[2], brow[4];
    #pragma unroll
    for (int mt = 0; mt < 2; ++mt) arow[mt] = (uint32_t)((wm + mt * 16 + mrow) * 80 + kb);
    #pragma unroll
    for (int np = 0; np < 4; ++np) brow[np] = (uint32_t)((wn + np * 16 + mrow) * 80 + kb);

    // v producer: 8 evals, one uint4 hi + one uint4 lo
    auto produce_v = [&](int ch, int st) {
        const int jbase = ch * 32 + jq * 8;
        float v[8];
        #pragma unroll
        for (int e = 0; e < 8; ++e) {
            int j = jbase + e;
            float dx = xi - sx[j], dy = yi - sy[j], dz = zi - sz[j];
            float d2 = fmaf(dx, dx, fmaf(dy, dy, dz * dz));
            float val = 0.0f;
            if (j != ig) {
                float inv = rsqrtf(d2);
                float d = d2 * inv;
                float fcut = (d < R_EXCL) ? 0.5f * (1.0f + __cosf(cc * d)) : 0.0f;
                val = (1.0f - fcut) * inv;
            }
            v[e] = val;
        }
        uint4 ph, pl;
        uint32_t* hw = (uint32_t*)&ph;
        uint32_t* lw = (uint32_t*)&pl;
        #pragma unroll
        for (int p = 0; p < 4; ++p) {
            uint32_t h = pack_bf16(v[2 * p], v[2 * p + 1]);
            hw[p] = h;
            lw[p] = pack_bf16(v[2 * p] - bf_lo(h), v[2 * p + 1] - bf_hi(h));
        }
        uint32_t off = (uint32_t)(G2_VS(st) + irow * 80 + jq * 16);
        *(uint4*)(sm + off) = ph;
        *(uint4*)(sm + off + 10240) = pl;
    };
    // q loader: 4 x 16B per thread (j<2 -> hi, j>=2 -> lo)
    auto load_q = [&](int ch, int st) {
        #pragma unroll
        for (int j = 0; j < 4; ++j) {
            int u = t + j * 512;
            int hi = (u < 1024);
            int u2 = u & 1023, row = u2 >> 2, c16 = u2 & 3;
            const char* src = (hi ? Bh : Bl) + (size_t)row * 1024 + ch * 64 + c16 * 16;
            CP_ASYNC16(sb + (uint32_t)(G2_QS(st) + (hi ? 0 : 20480) + row * 80 + c16 * 16), src);
        }
        CP_COMMIT();
    };

    // prologue
    produce_v(0, 0);
    load_q(0, 0);

    for (int ch = 0; ch < 16; ++ch) {
        __syncthreads();   // v[ch]+q-stage hazards resolved; prev MMA done
        if (ch + 1 < 16) {
            produce_v(ch + 1, (ch + 1) & 1);
            load_q(ch + 1, (ch + 1) & 1);
            CP_WAIT(1);
        } else {
            CP_WAIT(0);
        }
        gemm2_step(sb + (uint32_t)G2_VS(ch & 1), sb + (uint32_t)G2_QS(ch & 1), arow, brow, c);
    }
    __syncthreads();

    // Epilogue: rebuild q[m,f] in 2 f-halves (smem stride 132), out = 0.5*D*q
    float* sq = (float*)sm;
    float* outB = out + ((size_t)(s * N_ATOM) + m0) * F_DIM;
    #pragma unroll
    for (int h = 0; h < 2; ++h) {
        #pragma unroll
        for (int j = 0; j < 4; ++j) {
            int u = t + j * 512;
            int row = u >> 4, un = u & 15;
            size_t g = (size_t)(h * 128 + row) * 1024 + (size_t)m0 * 2 + un * 16;
            uint4 h4 = *(const uint4*)(Bh + g);
            uint4 l4 = *(const uint4*)(Bl + g);
            float* dst = sq + row * 132 + un * 8;
            uint32_t hw[4] = {h4.x, h4.y, h4.z, h4.w};
            uint32_t lw[4] = {l4.x, l4.y, l4.z, l4.w};
            #pragma unroll
            for (int wi = 0; wi < 4; ++wi) {
                dst[wi * 2 + 0] = bf_lo(hw[wi]) + bf_lo(lw[wi]);
                dst[wi * 2 + 1] = bf_hi(hw[wi]) + bf_hi(lw[wi]);
            }
        }
        __syncthreads();
        if ((wn >> 7) == h) {
            #pragma unroll
            for (int mt = 0; mt < 2; ++mt) {
                #pragma unroll
                for (int nt = 0; nt < 8; ++nt) {
                    const int ml = wm + mt * 16 + (lane >> 2);
                    const int fg = wn + nt * 8 + (lane & 3) * 2;     // global f
                    const int fl = fg - h * 128;                     // local to half
                    float* cf = c[mt][nt];
                    float q00 = sq[fl * 132 + ml], q01 = sq[(fl + 1) * 132 + ml];
                    float2 o0 = make_float2(0.5f * cf[0] * q00, 0.5f * cf[1] * q01);
                    *(float2*)(outB + (size_t)ml * F_DIM + fg) = o0;
                    float q10 = sq[fl * 132 + ml + 8], q11 = sq[(fl + 1) * 132 + ml + 8];
                    float2 o1 = make_float2(0.5f * cf[2] * q10, 0.5f * cf[3] * q11);
                    *(float2*)(outB + (size_t)(ml + 8) * F_DIM + fg) = o1;
                }
            }
        }
        __syncthreads();
    }
}

// ---------------------------------------------------------------------------
extern "C" void kernel_launch(void* const* d_in, const int* in_sizes, int n_in,
                              void* d_out, int out_size)
{
    const float* positions = (const float*)d_in[0]; // [32, 512, 3]
    const float* features  = (const float*)d_in[1]; // [16384, 256]
    const float* W         = (const float*)d_in[2]; // [256, 256]
    const float* b         = (const float*)d_in[3]; // [256]
    float* out             = (float*)d_out;         // [16384, 256]

    uint16_t *qhi, *qlo;
    cudaGetSymbolAddress((void**)&qhi, g_qhi);
    cudaGetSymbolAddress((void**)&qlo, g_qlo);

    cudaFuncSetAttribute(gemm1_mma, cudaFuncAttributeMaxDynamicSharedMemorySize, G1_SMEM);
    cudaFuncSetAttribute(gemm2_fused, cudaFuncAttributeMaxDynamicSharedMemorySize, G2_SMEM);

    // q^T (hi/lo bf16) = W @ feat^T + b  (128 CTAs, one wave)
    gemm1_mma<<<128, 512, G1_SMEM>>>(W, features, b, qhi, qlo);
    // out = 0.5 * (v @ q) * q, v generated in-kernel (128 CTAs, one wave)
    gemm2_fused<<<dim3(4, 32), 512, G2_SMEM>>>(positions, qhi, qlo, out);
}

// round 10
// speedup vs baseline: 3.0427x; 1.2005x over previous
#include <cuda_runtime.h>
#include <cuda_bf16.h>
#include <cuda_fp16.h>
#include <cstdint>
#include <math.h>

#define S_SYS 32
#define N_ATOM 512
#define F_DIM 256
#define R_EXCL 5.0f

// Scratch (__device__ globals; allocation-free rule).
__device__ __align__(16) uint16_t g_q16[(size_t)S_SYS * F_DIM * N_ATOM]; // 8 MB  q^T fp16
__device__ __align__(16) float    g_q32[(size_t)S_SYS * F_DIM * N_ATOM]; // 16 MB q^T fp32

// ---------------------------------------------------------------------------
// helpers
// ---------------------------------------------------------------------------
__device__ __forceinline__ uint32_t smem_u32(const void* p) {
    uint32_t a;
    asm("{ .reg .u64 t; cvta.to.shared.u64 t, %1; cvt.u32.u64 %0, t; }" : "=r"(a) : "l"(p));
    return a;
}
// pack two floats to bf16x2, first arg in LOW half
__device__ __forceinline__ uint32_t pack_bf16(float lo_elem, float hi_elem) {
    uint32_t r;
    asm("cvt.rn.bf16x2.f32 %0, %1, %2;" : "=r"(r) : "f"(hi_elem), "f"(lo_elem));
    return r;
}
__device__ __forceinline__ float bf_lo(uint32_t p) { return __uint_as_float(p << 16); }
__device__ __forceinline__ float bf_hi(uint32_t p) { return __uint_as_float(p & 0xFFFF0000u); }

__device__ __forceinline__ void mma_bf16(float* c, const uint32_t* a, uint32_t b0, uint32_t b1) {
    asm volatile(
        "mma.sync.aligned.m16n8k16.row.col.f32.bf16.bf16.f32 "
        "{%0,%1,%2,%3}, {%4,%5,%6,%7}, {%8,%9}, {%0,%1,%2,%3};"
        : "+f"(c[0]), "+f"(c[1]), "+f"(c[2]), "+f"(c[3])
        : "r"(a[0]), "r"(a[1]), "r"(a[2]), "r"(a[3]), "r"(b0), "r"(b1));
}
__device__ __forceinline__ void mma_f16(float* c, const uint32_t* a, uint32_t b0, uint32_t b1) {
    asm volatile(
        "mma.sync.aligned.m16n8k16.row.col.f32.f16.f16.f32 "
        "{%0,%1,%2,%3}, {%4,%5,%6,%7}, {%8,%9}, {%0,%1,%2,%3};"
        : "+f"(c[0]), "+f"(c[1]), "+f"(c[2]), "+f"(c[3])
        : "r"(a[0]), "r"(a[1]), "r"(a[2]), "r"(a[3]), "r"(b0), "r"(b1));
}
__device__ __forceinline__ void ldsm4(uint32_t* r, uint32_t addr) {
    asm volatile("ldmatrix.sync.aligned.m8n8.x4.shared.b16 {%0,%1,%2,%3}, [%4];"
                 : "=r"(r[0]), "=r"(r[1]), "=r"(r[2]), "=r"(r[3]) : "r"(addr));
}
#define CP_ASYNC16(dst, src) \
    asm volatile("cp.async.cg.shared.global [%0], [%1], 16;" :: "r"(dst), "l"(src))
#define CP_COMMIT() asm volatile("cp.async.commit_group;" ::: "memory")
#define CP_WAIT(n)  asm volatile("cp.async.wait_group %0;" :: "n"(n) : "memory")

// ===========================================================================
// GEMM1: qT[s][f][a] = sum_k W[f,k]*feat[a,k] + b[f]  (3-term bf16; fp16+fp32 out)
// BM(f)=256, BN(atom)=128, BK=32, 512 threads, warp tile 64x32 (4x4 warps).
// ===========================================================================
#define G1_RAWA(st) ((st) * 49152)
#define G1_RAWB(st) ((st) * 49152 + 32768)
#define G1_AH 98304
#define G1_AL 118784
#define G1_BH 139264
#define G1_BL 149504
#define G1_SMEM 159744

__device__ __forceinline__ void gemm1_step(
    uint32_t sb, const uint32_t arow[4], const uint32_t brow[2], float c[4][4][4])
{
    #pragma unroll
    for (int ks = 0; ks < 2; ++ks) {
        const uint32_t col = (uint32_t)(ks * 32);
        uint32_t ah[4][4], al[4][4], bh[2][4];
        #pragma unroll
        for (int mt = 0; mt < 4; ++mt) ldsm4(ah[mt], sb + G1_AH + arow[mt] + col);
        #pragma unroll
        for (int mt = 0; mt < 4; ++mt) ldsm4(al[mt], sb + G1_AL + arow[mt] + col);
        #pragma unroll
        for (int np = 0; np < 2; ++np) ldsm4(bh[np], sb + G1_BH + brow[np] + col);
        #pragma unroll
        for (int mt = 0; mt < 4; ++mt)
            #pragma unroll
            for (int nt = 0; nt < 4; ++nt)
                mma_bf16(c[mt][nt], ah[mt], bh[nt >> 1][nt & 1], bh[nt >> 1][(nt & 1) + 2]);
        #pragma unroll
        for (int mt = 0; mt < 4; ++mt)
            #pragma unroll
            for (int nt = 0; nt < 4; ++nt)
                mma_bf16(c[mt][nt], al[mt], bh[nt >> 1][nt & 1], bh[nt >> 1][(nt & 1) + 2]);
        uint32_t bl[2][4];
        #pragma unroll
        for (int np = 0; np < 2; ++np) ldsm4(bl[np], sb + G1_BL + brow[np] + col);
        #pragma unroll
        for (int mt = 0; mt < 4; ++mt)
            #pragma unroll
            for (int nt = 0; nt < 4; ++nt)
                mma_bf16(c[mt][nt], ah[mt], bl[nt >> 1][nt & 1], bl[nt >> 1][(nt & 1) + 2]);
    }
}

__global__ __launch_bounds__(512) void gemm1_mma(
    const float* __restrict__ W, const float* __restrict__ feat,
    const float* __restrict__ bias,
    uint16_t* __restrict__ q16, float* __restrict__ q32)
{
    extern __shared__ char sm[];
    const int t = threadIdx.x, lane = t & 31, w = t >> 5;
    const int wm = (w & 3) * 64, wn = (w >> 2) * 32;
    const int aB = blockIdx.x * 128;
    const uint32_t sb = smem_u32(sm);

    const char* Ag = (const char*)W;                            // 256 rows, 1024B stride
    const char* Bg = (const char*)(feat + (size_t)aB * F_DIM);  // 128 rows, 1024B stride

    float c[4][4][4] = {};
    const int mrow = (lane & 7) + ((lane >> 3) & 1) * 8;
    const int kb   = (lane >> 4) * 16;
    uint32_t arow[4], brow[2];
    #pragma unroll
    for (int mt = 0; mt < 4; ++mt) arow[mt] = (uint32_t)((wm + mt * 16 + mrow) * 80 + kb);
    #pragma unroll
    for (int np = 0; np < 2; ++np) brow[np] = (uint32_t)((wn + np * 16 + mrow) * 80 + kb);

    // prefetch raw chunk 0
    {
        #pragma unroll
        for (int j = 0; j < 6; ++j) {
            int u = t + j * 512;
            if (u < 2048) {
                int row = u >> 3, sg = u & 7;
                CP_ASYNC16(sb + G1_RAWA(0) + (uint32_t)(row * 128 + sg * 16),
                           Ag + (size_t)row * 1024 + sg * 16);
            } else {
                int u2 = u - 2048, row = u2 >> 3, sg = u2 & 7;
                CP_ASYNC16(sb + G1_RAWB(0) + (uint32_t)(row * 128 + sg * 16),
                           Bg + (size_t)row * 1024 + sg * 16);
            }
        }
        CP_COMMIT();
    }

    for (int ch = 0; ch < 8; ++ch) {
        if (ch + 1 < 8) {
            const int st = (ch + 1) & 1;
            #pragma unroll
            for (int j = 0; j < 6; ++j) {
                int u = t + j * 512;
                if (u < 2048) {
                    int row = u >> 3, sg = u & 7;
                    CP_ASYNC16(sb + G1_RAWA(st) + (uint32_t)(row * 128 + sg * 16),
                               Ag + (size_t)row * 1024 + (ch + 1) * 128 + sg * 16);
                } else {
                    int u2 = u - 2048, row = u2 >> 3, sg = u2 & 7;
                    CP_ASYNC16(sb + G1_RAWB(st) + (uint32_t)(row * 128 + sg * 16),
                               Bg + (size_t)row * 1024 + (ch + 1) * 128 + sg * 16);
                }
            }
            CP_COMMIT();
            CP_WAIT(1);
        } else {
            CP_WAIT(0);
        }
        __syncthreads();

        // convert raw fp32 -> bf16 hi/lo tiles (6 float4 per thread)
        {
            const char* rawA = sm + G1_RAWA(ch & 1);
            const char* rawB = sm + G1_RAWB(ch & 1);
            #pragma unroll
            for (int j = 0; j < 6; ++j) {
                int u = t + j * 512;
                const char* src;
                uint32_t dhi, dlo;
                int row, kq;
                if (u < 2048) {
                    row = u >> 3; kq = u & 7;
                    src = rawA + row * 128 + kq * 16;
                    dhi = (uint32_t)G1_AH; dlo = (uint32_t)G1_AL;
                } else {
                    int u2 = u - 2048; row = u2 >> 3; kq = u2 & 7;
                    src = rawB + row * 128 + kq * 16;
                    dhi = (uint32_t)G1_BH; dlo = (uint32_t)G1_BL;
                }
                float4 x = *(const float4*)src;
                uint32_t h01 = pack_bf16(x.x, x.y);
                uint32_t h23 = pack_bf16(x.z, x.w);
                uint32_t l01 = pack_bf16(x.x - bf_lo(h01), x.y - bf_hi(h01));
                uint32_t l23 = pack_bf16(x.z - bf_lo(h23), x.w - bf_hi(h23));
                uint32_t off = (uint32_t)(row * 80 + kq * 8);
                *(uint2*)(sm + dhi + off) = make_uint2(h01, h23);
                *(uint2*)(sm + dlo + off) = make_uint2(l01, l23);
            }
        }
        __syncthreads();

        gemm1_step(sb, arow, brow, c);
    }

    // epilogue: add bias, store qT as fp16 (mainloop operand) + fp32 (exact)
    const int sID = blockIdx.x >> 2;
    const int aLoc0 = (blockIdx.x & 3) * 128;
    uint16_t* qh16 = q16 + (size_t)sID * F_DIM * N_ATOM;
    float*    qh32 = q32 + (size_t)sID * F_DIM * N_ATOM;
    #pragma unroll
    for (int mt = 0; mt < 4; ++mt) {
        #pragma unroll
        for (int nt = 0; nt < 4; ++nt) {
            const int fg = wm + mt * 16 + (lane >> 2);
            const int ag = aLoc0 + wn + nt * 8 + (lane & 3) * 2;
            float* cf = c[mt][nt];
            float bv0 = bias[fg], bv1 = bias[fg + 8];
            float y0 = cf[0] + bv0, y1 = cf[1] + bv0;
            float y2 = cf[2] + bv1, y3 = cf[3] + bv1;
            *(float2*)(qh32 + (size_t)fg * N_ATOM + ag) = make_float2(y0, y1);
            *(float2*)(qh32 + (size_t)(fg + 8) * N_ATOM + ag) = make_float2(y2, y3);
            __half2 p01 = __floats2half2_rn(y0, y1);
            __half2 p23 = __floats2half2_rn(y2, y3);
            *(__half2*)(qh16 + (size_t)fg * N_ATOM + ag) = p01;
            *(__half2*)(qh16 + (size_t)(fg + 8) * N_ATOM + ag) = p23;
        }
    }
}

// ===========================================================================
// GEMM2 fused: out[s,m,f] = 0.5 * (sum_j v(m,j) q[j,f]) * q[m,f]
// fp16 path: v 2-split (vh+vl), q single fp16. BM=128, BN=256, BK=64.
// 512 threads, warp tile 32x64 (4m x 4n warps). 8 chunks, 1 sync each.
// smem: pos@0(6K) | V stages @6144 (2 x 36864: hi 18432 + lo 18432)
//       | Q stages @79872 (2 x 36864)    row stride 144B (128B data + pad)
// ===========================================================================
#define G2_VS(st) (6144 + (st) * 36864)
#define G2_QS(st) (79872 + (st) * 36864)
#define G2_SMEM 153600

__device__ __forceinline__ void gemm2_step(
    uint32_t vbase, uint32_t qbase,
    const uint32_t arow[2], const uint32_t brow[4], float c[2][8][4])
{
    #pragma unroll
    for (int ks = 0; ks < 4; ++ks) {
        const uint32_t col = (uint32_t)(ks * 32);
        uint32_t ah[2][4], bh[4][4];
        #pragma unroll
        for (int mt = 0; mt < 2; ++mt) ldsm4(ah[mt], vbase + arow[mt] + col);
        #pragma unroll
        for (int np = 0; np < 4; ++np) ldsm4(bh[np], qbase + brow[np] + col);
        #pragma unroll
        for (int mt = 0; mt < 2; ++mt)
            #pragma unroll
            for (int nt = 0; nt < 8; ++nt)
                mma_f16(c[mt][nt], ah[mt], bh[nt >> 1][nt & 1], bh[nt >> 1][(nt & 1) + 2]);
        uint32_t al[2][4];
        #pragma unroll
        for (int mt = 0; mt < 2; ++mt) ldsm4(al[mt], vbase + 18432 + arow[mt] + col);
        #pragma unroll
        for (int mt = 0; mt < 2; ++mt)
            #pragma unroll
            for (int nt = 0; nt < 8; ++nt)
                mma_f16(c[mt][nt], al[mt], bh[nt >> 1][nt & 1], bh[nt >> 1][(nt & 1) + 2]);
    }
}

__global__ __launch_bounds__(512) void gemm2_fused(
    const float* __restrict__ pos,
    const uint16_t* __restrict__ q16, const float* __restrict__ q32,
    float* __restrict__ out)
{
    extern __shared__ char sm[];
    const int t = threadIdx.x, lane = t & 31, w = t >> 5;
    const int wm = (w & 3) * 32, wn = (w >> 2) * 64;
    const int m0 = blockIdx.x * 128, s = blockIdx.y;
    const uint32_t sb = smem_u32(sm);

    float* sx = (float*)(sm);
    float* sy = (float*)(sm + 2048);
    float* sz = (float*)(sm + 4096);

    // stage all positions of system s (512 threads -> 1 atom each)
    const float* ps = pos + (size_t)s * N_ATOM * 3;
    {
        float3 p = *(const float3*)(ps + t * 3);
        sx[t] = p.x; sy[t] = p.y; sz[t] = p.z;
    }
    __syncthreads();

    const int irow = t >> 2;            // 0..127 (v row)
    const int jq   = (t & 3);           // 16-j group within 64-chunk
    const int ig   = m0 + irow;
    const float xi = sx[ig], yi = sy[ig], zi = sz[ig];
    const float cc = 3.14159265358979323846f / R_EXCL;

    const char* Bq = (const char*)(q16 + (size_t)s * F_DIM * N_ATOM);  // 1024B row stride

    float c[2][8][4] = {};
    const int mrow = (lane & 7) + ((lane >> 3) & 1) * 8;
    const int kb   = (lane >> 4) * 16;
    uint32_t arow[2], brow[4];
    #pragma unroll
    for (int mt = 0; mt < 2; ++mt) arow[mt] = (uint32_t)((wm + mt * 16 + mrow) * 144 + kb);
    #pragma unroll
    for (int np = 0; np < 4; ++np) brow[np] = (uint32_t)((wn + np * 16 + mrow) * 144 + kb);

    // v producer: 16 evals -> fp16 hi (2x uint4) + fp16 lo (2x uint4)
    auto produce_v = [&](int ch, int st) {
        const int jbase = ch * 64 + jq * 16;
        __half2 hq[8], lq[8];
        #pragma unroll
        for (int p = 0; p < 8; ++p) {
            float vv[2];
            #pragma unroll
            for (int e = 0; e < 2; ++e) {
                int j = jbase + p * 2 + e;
                float dx = xi - sx[j], dy = yi - sy[j], dz = zi - sz[j];
                float d2 = fmaf(dx, dx, fmaf(dy, dy, dz * dz));
                float val = 0.0f;
                if (j != ig) {
                    float inv = rsqrtf(d2);
                    float d = d2 * inv;
                    float fcut = (d < R_EXCL) ? 0.5f * (1.0f + __cosf(cc * d)) : 0.0f;
                    val = (1.0f - fcut) * inv;
                }
                vv[e] = val;
            }
            __half h0 = __float2half_rn(vv[0]), h1 = __float2half_rn(vv[1]);
            hq[p] = __halves2half2(h0, h1);
            lq[p] = __floats2half2_rn(vv[0] - __half2float(h0), vv[1] - __half2float(h1));
        }
        uint32_t off = (uint32_t)(G2_VS(st) + irow * 144 + jq * 32);
        *(uint4*)(sm + off)          = ((uint4*)hq)[0];
        *(uint4*)(sm + off + 16)     = ((uint4*)hq)[1];
        *(uint4*)(sm + off + 18432)      = ((uint4*)lq)[0];
        *(uint4*)(sm + off + 18432 + 16) = ((uint4*)lq)[1];
    };
    // q loader: 256 rows x 128B per chunk = 2048 x 16B, 4 per thread
    auto load_q = [&](int ch, int st) {
        #pragma unroll
        for (int j = 0; j < 4; ++j) {
            int u = t + j * 512;
            int row = u >> 3, sg = u & 7;
            const char* src = Bq + (size_t)row * 1024 + ch * 128 + sg * 16;
            CP_ASYNC16(sb + (uint32_t)(G2_QS(st) + row * 144 + sg * 16), src);
        }
        CP_COMMIT();
    };

    // prologue
    produce_v(0, 0);
    load_q(0, 0);

    for (int ch = 0; ch < 8; ++ch) {
        __syncthreads();   // all warps done with stage (ch+1)&1 buffers
        if (ch + 1 < 8) {
            produce_v(ch + 1, (ch + 1) & 1);
            load_q(ch + 1, (ch + 1) & 1);
            CP_WAIT(1);
        } else {
            CP_WAIT(0);
        }
        gemm2_step(sb + (uint32_t)G2_VS(ch & 1), sb + (uint32_t)G2_QS(ch & 1), arow, brow, c);
    }
    __syncthreads();

    // Epilogue: stage exact fp32 q[m,f] in 2 f-halves (smem stride 132 floats)
    const float* Q32 = q32 + (size_t)s * F_DIM * N_ATOM;
    float* sq = (float*)sm;
    float* outB = out + ((size_t)(s * N_ATOM) + m0) * F_DIM;
    #pragma unroll
    for (int h = 0; h < 2; ++h) {
        #pragma unroll
        for (int j = 0; j < 8; ++j) {
            int u = t + j * 512;
            int row = u >> 5, un = u & 31;
            float4 x = *(const float4*)(Q32 + (size_t)(h * 128 + row) * N_ATOM + m0 + un * 4);
            *(float4*)(sq + row * 132 + un * 4) = x;
        }
        __syncthreads();
        if ((wn >> 7) == h) {
            #pragma unroll
            for (int mt = 0; mt < 2; ++mt) {
                #pragma unroll
                for (int nt = 0; nt < 8; ++nt) {
                    const int ml = wm + mt * 16 + (lane >> 2);
                    const int fg = wn + nt * 8 + (lane & 3) * 2;     // global f
                    const int fl = fg - h * 128;                     // local to half
                    float* cf = c[mt][nt];
                    float q00 = sq[fl * 132 + ml], q01 = sq[(fl + 1) * 132 + ml];
                    float2 o0 = make_float2(0.5f * cf[0] * q00, 0.5f * cf[1] * q01);
                    *(float2*)(outB + (size_t)ml * F_DIM + fg) = o0;
                    float q10 = sq[fl * 132 + ml + 8], q11 = sq[(fl + 1) * 132 + ml + 8];
                    float2 o1 = make_float2(0.5f * cf[2] * q10, 0.5f * cf[3] * q11);
                    *(float2*)(outB + (size_t)(ml + 8) * F_DIM + fg) = o1;
                }
            }
        }
        __syncthreads();
    }
}

// ---------------------------------------------------------------------------
extern "C" void kernel_launch(void* const* d_in, const int* in_sizes, int n_in,
                              void* d_out, int out_size)
{
    const float* positions = (const float*)d_in[0]; // [32, 512, 3]
    const float* features  = (const float*)d_in[1]; // [16384, 256]
    const float* W         = (const float*)d_in[2]; // [256, 256]
    const float* b         = (const float*)d_in[3]; // [256]
    float* out             = (float*)d_out;         // [16384, 256]

    uint16_t* q16; float* q32;
    cudaGetSymbolAddress((void**)&q16, g_q16);
    cudaGetSymbolAddress((void**)&q32, g_q32);

    cudaFuncSetAttribute(gemm1_mma, cudaFuncAttributeMaxDynamicSharedMemorySize, G1_SMEM);
    cudaFuncSetAttribute(gemm2_fused, cudaFuncAttributeMaxDynamicSharedMemorySize, G2_SMEM);

    // q^T = W @ feat^T + b  (3-term bf16 -> fp16 + fp32 outputs)
    gemm1_mma<<<128, 512, G1_SMEM>>>(W, features, b, q16, q32);
    // out = 0.5 * (v @ q) * q, v generated in-kernel (fp16 2-term)
    gemm2_fused<<<dim3(4, 32), 512, G2_SMEM>>>(positions, q16, q32, out);
}

// round 12
// speedup vs baseline: 3.4352x; 1.1290x over previous
#include <cuda_runtime.h>
#include <cuda_bf16.h>
#include <cuda_fp16.h>
#include <cstdint>
#include <math.h>

#define S_SYS 32
#define N_ATOM 512
#define F_DIM 256
#define R_EXCL 5.0f

// Scratch (__device__ globals; allocation-free rule).
__device__ __align__(16) uint16_t g_q16[(size_t)S_SYS * F_DIM * N_ATOM]; // 8 MB  q^T fp16
__device__ __align__(16) float    g_q32[(size_t)S_SYS * F_DIM * N_ATOM]; // 16 MB q^T fp32

// ---------------------------------------------------------------------------
// helpers
// ---------------------------------------------------------------------------
__device__ __forceinline__ uint32_t smem_u32(const void* p) {
    uint32_t a;
    asm("{ .reg .u64 t; cvta.to.shared.u64 t, %1; cvt.u32.u64 %0, t; }" : "=r"(a) : "l"(p));
    return a;
}
// pack two floats to bf16x2, first arg in LOW half
__device__ __forceinline__ uint32_t pack_bf16(float lo_elem, float hi_elem) {
    uint32_t r;
    asm("cvt.rn.bf16x2.f32 %0, %1, %2;" : "=r"(r) : "f"(hi_elem), "f"(lo_elem));
    return r;
}
__device__ __forceinline__ float bf_lo(uint32_t p) { return __uint_as_float(p << 16); }
__device__ __forceinline__ float bf_hi(uint32_t p) { return __uint_as_float(p & 0xFFFF0000u); }

__device__ __forceinline__ void mma_bf16(float* c, const uint32_t* a, uint32_t b0, uint32_t b1) {
    asm volatile(
        "mma.sync.aligned.m16n8k16.row.col.f32.bf16.bf16.f32 "
        "{%0,%1,%2,%3}, {%4,%5,%6,%7}, {%8,%9}, {%0,%1,%2,%3};"
        : "+f"(c[0]), "+f"(c[1]), "+f"(c[2]), "+f"(c[3])
        : "r"(a[0]), "r"(a[1]), "r"(a[2]), "r"(a[3]), "r"(b0), "r"(b1));
}
__device__ __forceinline__ void mma_f16(float* c, const uint32_t* a, uint32_t b0, uint32_t b1) {
    asm volatile(
        "mma.sync.aligned.m16n8k16.row.col.f32.f16.f16.f32 "
        "{%0,%1,%2,%3}, {%4,%5,%6,%7}, {%8,%9}, {%0,%1,%2,%3};"
        : "+f"(c[0]), "+f"(c[1]), "+f"(c[2]), "+f"(c[3])
        : "r"(a[0]), "r"(a[1]), "r"(a[2]), "r"(a[3]), "r"(b0), "r"(b1));
}
__device__ __forceinline__ void ldsm4(uint32_t* r, uint32_t addr) {
    asm volatile("ldmatrix.sync.aligned.m8n8.x4.shared.b16 {%0,%1,%2,%3}, [%4];"
                 : "=r"(r[0]), "=r"(r[1]), "=r"(r[2]), "=r"(r[3]) : "r"(addr));
}
#define CP_ASYNC16(dst, src) \
    asm volatile("cp.async.cg.shared.global [%0], [%1], 16;" :: "r"(dst), "l"(src))
#define CP_COMMIT() asm volatile("cp.async.commit_group;" ::: "memory")
#define CP_WAIT(n)  asm volatile("cp.async.wait_group %0;" :: "n"(n) : "memory")

// ===========================================================================
// GEMM1: qT[s][f][a] = sum_k W[f,k]*feat[a,k] + b[f]  (3-term bf16; fp16+fp32 out)
// BM(f)=256, BN(atom)=128, BK=32, 512 threads, warp tile 64x32 (4x4 warps).
// ===========================================================================
#define G1_RAWA(st) ((st) * 49152)
#define G1_RAWB(st) ((st) * 49152 + 32768)
#define G1_AH 98304
#define G1_AL 118784
#define G1_BH 139264
#define G1_BL 149504
#define G1_SMEM 159744

__device__ __forceinline__ void gemm1_step(
    uint32_t sb, const uint32_t arow[4], const uint32_t brow[2], float c[4][4][4])
{
    #pragma unroll
    for (int ks = 0; ks < 2; ++ks) {
        const uint32_t col = (uint32_t)(ks * 32);
        uint32_t ah[4][4], al[4][4], bh[2][4];
        #pragma unroll
        for (int mt = 0; mt < 4; ++mt) ldsm4(ah[mt], sb + G1_AH + arow[mt] + col);
        #pragma unroll
        for (int mt = 0; mt < 4; ++mt) ldsm4(al[mt], sb + G1_AL + arow[mt] + col);
        #pragma unroll
        for (int np = 0; np < 2; ++np) ldsm4(bh[np], sb + G1_BH + brow[np] + col);
        #pragma unroll
        for (int mt = 0; mt < 4; ++mt)
            #pragma unroll
            for (int nt = 0; nt < 4; ++nt)
                mma_bf16(c[mt][nt], ah[mt], bh[nt >> 1][nt & 1], bh[nt >> 1][(nt & 1) + 2]);
        #pragma unroll
        for (int mt = 0; mt < 4; ++mt)
            #pragma unroll
            for (int nt = 0; nt < 4; ++nt)
                mma_bf16(c[mt][nt], al[mt], bh[nt >> 1][nt & 1], bh[nt >> 1][(nt & 1) + 2]);
        uint32_t bl[2][4];
        #pragma unroll
        for (int np = 0; np < 2; ++np) ldsm4(bl[np], sb + G1_BL + brow[np] + col);
        #pragma unroll
        for (int mt = 0; mt < 4; ++mt)
            #pragma unroll
            for (int nt = 0; nt < 4; ++nt)
                mma_bf16(c[mt][nt], ah[mt], bl[nt >> 1][nt & 1], bl[nt >> 1][(nt & 1) + 2]);
    }
}

__global__ __launch_bounds__(512) void gemm1_mma(
    const float* __restrict__ W, const float* __restrict__ feat,
    const float* __restrict__ bias,
    uint16_t* __restrict__ q16, float* __restrict__ q32)
{
    extern __shared__ char sm[];
    const int t = threadIdx.x, lane = t & 31, w = t >> 5;
    const int wm = (w & 3) * 64, wn = (w >> 2) * 32;
    const int aB = blockIdx.x * 128;
    const uint32_t sb = smem_u32(sm);

    const char* Ag = (const char*)W;                            // 256 rows, 1024B stride
    const char* Bg = (const char*)(feat + (size_t)aB * F_DIM);  // 128 rows, 1024B stride

    float c[4][4][4] = {};
    const int mrow = (lane & 7) + ((lane >> 3) & 1) * 8;
    const int kb   = (lane >> 4) * 16;
    uint32_t arow[4], brow[2];
    #pragma unroll
    for (int mt = 0; mt < 4; ++mt) arow[mt] = (uint32_t)((wm + mt * 16 + mrow) * 80 + kb);
    #pragma unroll
    for (int np = 0; np < 2; ++np) brow[np] = (uint32_t)((wn + np * 16 + mrow) * 80 + kb);

    // prefetch raw chunk 0
    {
        #pragma unroll
        for (int j = 0; j < 6; ++j) {
            int u = t + j * 512;
            if (u < 2048) {
                int row = u >> 3, sg = u & 7;
                CP_ASYNC16(sb + G1_RAWA(0) + (uint32_t)(row * 128 + sg * 16),
                           Ag + (size_t)row * 1024 + sg * 16);
            } else {
                int u2 = u - 2048, row = u2 >> 3, sg = u2 & 7;
                CP_ASYNC16(sb + G1_RAWB(0) + (uint32_t)(row * 128 + sg * 16),
                           Bg + (size_t)row * 1024 + sg * 16);
            }
        }
        CP_COMMIT();
    }

    for (int ch = 0; ch < 8; ++ch) {
        if (ch + 1 < 8) {
            const int st = (ch + 1) & 1;
            #pragma unroll
            for (int j = 0; j < 6; ++j) {
                int u = t + j * 512;
                if (u < 2048) {
                    int row = u >> 3, sg = u & 7;
                    CP_ASYNC16(sb + G1_RAWA(st) + (uint32_t)(row * 128 + sg * 16),
                               Ag + (size_t)row * 1024 + (ch + 1) * 128 + sg * 16);
                } else {
                    int u2 = u - 2048, row = u2 >> 3, sg = u2 & 7;
                    CP_ASYNC16(sb + G1_RAWB(st) + (uint32_t)(row * 128 + sg * 16),
                               Bg + (size_t)row * 1024 + (ch + 1) * 128 + sg * 16);
                }
            }
            CP_COMMIT();
            CP_WAIT(1);
        } else {
            CP_WAIT(0);
        }
        __syncthreads();

        // convert raw fp32 -> bf16 hi/lo tiles (6 float4 per thread)
        {
            const char* rawA = sm + G1_RAWA(ch & 1);
            const char* rawB = sm + G1_RAWB(ch & 1);
            #pragma unroll
            for (int j = 0; j < 6; ++j) {
                int u = t + j * 512;
                const char* src;
                uint32_t dhi, dlo;
                int row, kq;
                if (u < 2048) {
                    row = u >> 3; kq = u & 7;
                    src = rawA + row * 128 + kq * 16;
                    dhi = (uint32_t)G1_AH; dlo = (uint32_t)G1_AL;
                } else {
                    int u2 = u - 2048; row = u2 >> 3; kq = u2 & 7;
                    src = rawB + row * 128 + kq * 16;
                    dhi = (uint32_t)G1_BH; dlo = (uint32_t)G1_BL;
                }
                float4 x = *(const float4*)src;
                uint32_t h01 = pack_bf16(x.x, x.y);
                uint32_t h23 = pack_bf16(x.z, x.w);
                uint32_t l01 = pack_bf16(x.x - bf_lo(h01), x.y - bf_hi(h01));
                uint32_t l23 = pack_bf16(x.z - bf_lo(h23), x.w - bf_hi(h23));
                uint32_t off = (uint32_t)(row * 80 + kq * 8);
                *(uint2*)(sm + dhi + off) = make_uint2(h01, h23);
                *(uint2*)(sm + dlo + off) = make_uint2(l01, l23);
            }
        }
        __syncthreads();

        gemm1_step(sb, arow, brow, c);
    }

    // epilogue: add bias, store qT as fp16 (mainloop operand) + fp32 (exact)
    const int sID = blockIdx.x >> 2;
    const int aLoc0 = (blockIdx.x & 3) * 128;
    uint16_t* qh16 = q16 + (size_t)sID * F_DIM * N_ATOM;
    float*    qh32 = q32 + (size_t)sID * F_DIM * N_ATOM;
    #pragma unroll
    for (int mt = 0; mt < 4; ++mt) {
        #pragma unroll
        for (int nt = 0; nt < 4; ++nt) {
            const int fg = wm + mt * 16 + (lane >> 2);
            const int ag = aLoc0 + wn + nt * 8 + (lane & 3) * 2;
            float* cf = c[mt][nt];
            float bv0 = bias[fg], bv1 = bias[fg + 8];
            float y0 = cf[0] + bv0, y1 = cf[1] + bv0;
            float y2 = cf[2] + bv1, y3 = cf[3] + bv1;
            *(float2*)(qh32 + (size_t)fg * N_ATOM + ag) = make_float2(y0, y1);
            *(float2*)(qh32 + (size_t)(fg + 8) * N_ATOM + ag) = make_float2(y2, y3);
            __half2 p01 = __floats2half2_rn(y0, y1);
            __half2 p23 = __floats2half2_rn(y2, y3);
            *(__half2*)(qh16 + (size_t)fg * N_ATOM + ag) = p01;
            *(__half2*)(qh16 + (size_t)(fg + 8) * N_ATOM + ag) = p23;
        }
    }
}

// ===========================================================================
// GEMM2 fused: out[s,m,f] = 0.5 * (sum_j v(m,j) q[j,f]) * q[m,f]
// fp16 path: v SINGLE fp16, q single fp16 -> 1 MMA group. BM=128, BN=256, BK=64.
// 512 threads, warp tile 32x64 (4m x 4n warps). 8 chunks, 1 sync each.
// smem: pos@0(6K) | V stages @6144 (2 x 18432) | Q stages @43008 (3 x 36864)
// row stride 144B (128B data + 16B pad; conflict-free for ldmatrix).
// ===========================================================================
#define G2_VS(st) (6144 + (st) * 18432)
#define G2_QS(st) (43008 + (st) * 36864)
#define G2_SMEM 153600

__device__ __forceinline__ void gemm2_step(
    uint32_t vbase, uint32_t qbase,
    const uint32_t arow[2], const uint32_t brow[4], float c[2][8][4])
{
    #pragma unroll
    for (int ks = 0; ks < 4; ++ks) {
        const uint32_t col = (uint32_t)(ks * 32);
        uint32_t ah[2][4], bh[4][4];
        #pragma unroll
        for (int mt = 0; mt < 2; ++mt) ldsm4(ah[mt], vbase + arow[mt] + col);
        #pragma unroll
        for (int np = 0; np < 4; ++np) ldsm4(bh[np], qbase + brow[np] + col);
        #pragma unroll
        for (int mt = 0; mt < 2; ++mt)
            #pragma unroll
            for (int nt = 0; nt < 8; ++nt)
                mma_f16(c[mt][nt], ah[mt], bh[nt >> 1][nt & 1], bh[nt >> 1][(nt & 1) + 2]);
    }
}

__global__ __launch_bounds__(512) void gemm2_fused(
    const float* __restrict__ pos,
    const uint16_t* __restrict__ q16, const float* __restrict__ q32,
    float* __restrict__ out)
{
    extern __shared__ char sm[];
    const int t = threadIdx.x, lane = t & 31, w = t >> 5;
    const int wm = (w & 3) * 32, wn = (w >> 2) * 64;
    const int m0 = blockIdx.x * 128, s = blockIdx.y;
    const uint32_t sb = smem_u32(sm);

    float* sx = (float*)(sm);
    float* sy = (float*)(sm + 2048);
    float* sz = (float*)(sm + 4096);

    // stage all positions of system s (512 threads -> 1 atom each)
    const float* ps = pos + (size_t)s * N_ATOM * 3;
    {
        float3 p = *(const float3*)(ps + t * 3);
        sx[t] = p.x; sy[t] = p.y; sz[t] = p.z;
    }
    __syncthreads();

    const int irow = t >> 2;            // 0..127 (v row)
    const int jq   = (t & 3);           // 16-j group within 64-chunk
    const int ig   = m0 + irow;
    const float xi = sx[ig], yi = sy[ig], zi = sz[ig];
    const float cc = 3.14159265358979323846f / R_EXCL;

    const char* Bq = (const char*)(q16 + (size_t)s * F_DIM * N_ATOM);  // 1024B row stride

    float c[2][8][4] = {};
    const int mrow = (lane & 7) + ((lane >> 3) & 1) * 8;
    const int kb   = (lane >> 4) * 16;
    uint32_t arow[2], brow[4];
    #pragma unroll
    for (int mt = 0; mt < 2; ++mt) arow[mt] = (uint32_t)((wm + mt * 16 + mrow) * 144 + kb);
    #pragma unroll
    for (int np = 0; np < 4; ++np) brow[np] = (uint32_t)((wn + np * 16 + mrow) * 144 + kb);

    // v producer: 16 evals -> single fp16 (2x uint4)
    auto produce_v = [&](int ch, int st) {
        const int jbase = ch * 64 + jq * 16;
        __half2 hq[8];
        #pragma unroll
        for (int p = 0; p < 8; ++p) {
            float vv[2];
            #pragma unroll
            for (int e = 0; e < 2; ++e) {
                int j = jbase + p * 2 + e;
                float dx = xi - sx[j], dy = yi - sy[j], dz = zi - sz[j];
                float d2 = fmaf(dx, dx, fmaf(dy, dy, dz * dz));
                float val = 0.0f;
                if (j != ig) {
                    float inv = rsqrtf(d2);
                    float d = d2 * inv;
                    float fcut = (d < R_EXCL) ? 0.5f * (1.0f + __cosf(cc * d)) : 0.0f;
                    val = (1.0f - fcut) * inv;
                }
                vv[e] = val;
            }
            hq[p] = __floats2half2_rn(vv[0], vv[1]);
        }
        uint32_t off = (uint32_t)(G2_VS(st) + irow * 144 + jq * 32);
        *(uint4*)(sm + off)      = ((uint4*)hq)[0];
        *(uint4*)(sm + off + 16) = ((uint4*)hq)[1];
    };
    // q loader: 256 rows x 128B per chunk = 2048 x 16B, 4 per thread
    auto load_q = [&](int ch, int st) {
        #pragma unroll
        for (int j = 0; j < 4; ++j) {
            int u = t + j * 512;
            int row = u >> 3, sg = u & 7;
            const char* src = Bq + (size_t)row * 1024 + ch * 128 + sg * 16;
            CP_ASYNC16(sb + (uint32_t)(G2_QS(st) + row * 144 + sg * 16), src);
        }
        CP_COMMIT();
    };

    // prologue: v[0], q[0], q[1]
    produce_v(0, 0);
    load_q(0, 0);
    load_q(1, 1);

    for (int ch = 0; ch < 8; ++ch) {
        __syncthreads();   // prev-chunk MMA done -> reused v/q stages free
        if (ch + 1 < 8) produce_v(ch + 1, (ch + 1) & 1);
        if (ch + 2 < 8) {
            load_q(ch + 2, (ch + 2) % 3);
            CP_WAIT(2);
        } else if (ch + 1 < 8) {
            CP_WAIT(1);
        } else {
            CP_WAIT(0);
        }
        gemm2_step(sb + (uint32_t)G2_VS(ch & 1), sb + (uint32_t)G2_QS(ch % 3), arow, brow, c);
    }
    __syncthreads();

    // Epilogue: stage exact fp32 q[m,f] in 2 f-halves (smem stride 132 floats)
    const float* Q32 = q32 + (size_t)s * F_DIM * N_ATOM;
    float* sq = (float*)sm;
    float* outB = out + ((size_t)(s * N_ATOM) + m0) * F_DIM;
    #pragma unroll
    for (int h = 0; h < 2; ++h) {
        #pragma unroll
        for (int j = 0; j < 8; ++j) {
            int u = t + j * 512;
            int row = u >> 5, un = u & 31;
            float4 x = *(const float4*)(Q32 + (size_t)(h * 128 + row) * N_ATOM + m0 + un * 4);
            *(float4*)(sq + row * 132 + un * 4) = x;
        }
        __syncthreads();
        if ((wn >> 7) == h) {
            #pragma unroll
            for (int mt = 0; mt < 2; ++mt) {
                #pragma unroll
                for (int nt = 0; nt < 8; ++nt) {
                    const int ml = wm + mt * 16 + (lane >> 2);
                    const int fg = wn + nt * 8 + (lane & 3) * 2;     // global f
                    const int fl = fg - h * 128;                     // local to half
                    float* cf = c[mt][nt];
                    float q00 = sq[fl * 132 + ml], q01 = sq[(fl + 1) * 132 + ml];
                    float2 o0 = make_float2(0.5f * cf[0] * q00, 0.5f * cf[1] * q01);
                    *(float2*)(outB + (size_t)ml * F_DIM + fg) = o0;
                    float q10 = sq[fl * 132 + ml + 8], q11 = sq[(fl + 1) * 132 + ml + 8];
                    float2 o1 = make_float2(0.5f * cf[2] * q10, 0.5f * cf[3] * q11);
                    *(float2*)(outB + (size_t)(ml + 8) * F_DIM + fg) = o1;
                }
            }
        }
        __syncthreads();
    }
}

// ---------------------------------------------------------------------------
extern "C" void kernel_launch(void* const* d_in, const int* in_sizes, int n_in,
                              void* d_out, int out_size)
{
    const float* positions = (const float*)d_in[0]; // [32, 512, 3]
    const float* features  = (const float*)d_in[1]; // [16384, 256]
    const float* W         = (const float*)d_in[2]; // [256, 256]
    const float* b         = (const float*)d_in[3]; // [256]
    float* out             = (float*)d_out;         // [16384, 256]

    uint16_t* q16; float* q32;
    cudaGetSymbolAddress((void**)&q16, g_q16);
    cudaGetSymbolAddress((void**)&q32, g_q32);

    cudaFuncSetAttribute(gemm1_mma, cudaFuncAttributeMaxDynamicSharedMemorySize, G1_SMEM);
    cudaFuncSetAttribute(gemm2_fused, cudaFuncAttributeMaxDynamicSharedMemorySize, G2_SMEM);

    // q^T = W @ feat^T + b  (3-term bf16 -> fp16 + fp32 outputs)
    gemm1_mma<<<128, 512, G1_SMEM>>>(W, features, b, q16, q32);
    // out = 0.5 * (v @ q) * q, v single fp16 generated in-kernel
    gemm2_fused<<<dim3(4, 32), 512, G2_SMEM>>>(positions, q16, q32, out);
}